// round 7
// baseline (speedup 1.0000x reference)
#include <cuda_runtime.h>
#include <cuda_fp16.h>
#include <math.h>
#include <stdint.h>

#define NB 8
#define NC 512
#define NL 8192
#define NA 7
#define NPA (NL*NA)
#define PRE_K 600
#define POST_K 100
#define NMW 19
#define LPAD 8194

#define OFF_OBJ  0
#define SZ_OBJ   (NB*NPA)
#define OFF_REG  (SZ_OBJ)
#define SZ_REG   (NB*NPA*2)
#define OFF_ANCH (OFF_REG + SZ_REG)
#define SZ_ANCH  (NPA*2)
#define OFF_PROPS (OFF_ANCH + SZ_ANCH)
#define SZ_PROPS (NB*POST_K*2)
#define OFF_PSC  (OFF_PROPS + SZ_PROPS)
#define OFF_PMASK (OFF_PSC + NB*POST_K)

__device__ float g_h[(size_t)NB*NC*NL];
__device__ float g_boxes[(size_t)NB*NPA*2];
__device__ float g_scores[(size_t)NB*NPA];
__device__ __align__(256) __half g_fT1[(size_t)NB*LPAD*NC];
__device__ __align__(256) __half g_fT2[(size_t)NB*LPAD*NC];
__device__ __align__(256) __half g_W1[3*512*512];
__device__ __align__(256) __half g_W2[3*512*512];

__constant__ float c_lens[NA] = {1.f,2.f,3.f,4.f,5.f,7.f,9.f};

__device__ __forceinline__ uint32_t smem_u32(const void* p) {
    uint32_t a;
    asm("{ .reg .u64 t; cvta.to.shared.u64 t, %1; cvt.u32.u64 %0, t; }" : "=r"(a) : "l"(p));
    return a;
}
#define CP16(dst,src) asm volatile("cp.async.cg.shared.global [%0], [%1], 16;"::"r"(dst),"l"(src))
#define CPCOMMIT() asm volatile("cp.async.commit_group;":::"memory")
#define CPWAIT2() asm volatile("cp.async.wait_group 2;":::"memory")
#define LDSM4(r,addr) asm volatile( \
    "ldmatrix.sync.aligned.m8n8.x4.shared.b16 {%0,%1,%2,%3}, [%4];" \
    : "=r"((r)[0]),"=r"((r)[1]),"=r"((r)[2]),"=r"((r)[3]) : "r"(addr))
#define MMA(d,a,b0,b1) asm volatile( \
    "mma.sync.aligned.m16n8k16.row.col.f32.f16.f16.f32 " \
    "{%0,%1,%2,%3}, {%4,%5,%6,%7}, {%8,%9}, {%0,%1,%2,%3};" \
    : "+f"((d)[0]),"+f"((d)[1]),"+f"((d)[2]),"+f"((d)[3]) \
    : "r"((a)[0]),"r"((a)[1]),"r"((a)[2]),"r"((a)[3]),"r"(b0),"r"(b1))

// ---- prep: 2-limb fp16 splits ----
__global__ void splitw_kernel(const float* __restrict__ w) {
    int idx = blockIdx.x*256 + threadIdx.x;
    if (idx >= 3*512*512) return;
    int c = idx & 511, o = (idx >> 9) & 511, t = idx >> 18;
    float v = w[(size_t)o*1536 + c*3 + t];
    __half a1 = __float2half_rn(v);
    g_W1[idx] = a1;
    g_W2[idx] = __float2half_rn(v - __half2float(a1));
}
__global__ void pad_kernel() {
    int b = blockIdx.x, c = threadIdx.x;
    __half z = __float2half_rn(0.f);
    size_t r0 = ((size_t)b*LPAD)*NC + c, r1 = ((size_t)b*LPAD + (LPAD-1))*NC + c;
    g_fT1[r0]=z; g_fT2[r0]=z;
    g_fT1[r1]=z; g_fT2[r1]=z;
}
__global__ __launch_bounds__(256)
void splitfeat_kernel(const float* __restrict__ feat) {
    __shared__ float tile[64][65];
    int b = blockIdx.z, c0 = blockIdx.y*64, l0 = blockIdx.x*64;
    int tj = threadIdx.x & 63, ti = threadIdx.x >> 6;
    const float* src = feat + ((size_t)b*NC + c0)*NL + l0;
#pragma unroll
    for (int i = ti; i < 64; i += 4) tile[i][tj] = src[(size_t)i*NL + tj];
    __syncthreads();
#pragma unroll
    for (int lj = ti; lj < 64; lj += 4) {
        float v = tile[tj][lj];
        __half a1 = __float2half_rn(v);
        size_t dst = ((size_t)b*LPAD + (l0 + lj + 1))*NC + c0 + tj;
        g_fT1[dst] = a1;
        g_fT2[dst] = __float2half_rn(v - __half2float(a1));
    }
}

// ---- conv via mma.sync fp16 2-limb: CTA 128(o) x 128(l), 4 warps 64x64 ----
// 96 stages of k=16, 4-stage smem ring, prefetch distance 3.
#define ROWB   48u                 // 16 cols * 2B + 16B pad
#define TILE_B (128u*ROWB)         // 6144 B
#define STG_B  (4u*TILE_B)         // 24576 B (W1,W2,F1,F2)
#define CONV_SMEM (4u*STG_B)       // 98304 B

__device__ __forceinline__ void load_stage(uint32_t sb, int s,
                                           int b, int l0, int o0, int tid) {
    const uint32_t buf = sb + (uint32_t)(s & 3)*STG_B;
    const int t = s >> 5, c0 = (s & 31) << 4;
    const __half* GW[2] = {g_W1, g_W2};
    const __half* GF[2] = {g_fT1, g_fT2};
    // 128 threads: each thread loads row=tid, both 8-col halves, for 4 tiles
#pragma unroll
    for (int L = 0; L < 2; L++) {
        size_t ws = ((size_t)(t*512 + o0 + tid))*512 + c0;
        CP16(buf + L*TILE_B + tid*ROWB,      GW[L] + ws);
        CP16(buf + L*TILE_B + tid*ROWB + 16, GW[L] + ws + 8);
        size_t fs = ((size_t)b*LPAD + (size_t)(l0 + tid + t))*512 + c0;
        CP16(buf + (2+L)*TILE_B + tid*ROWB,      GF[L] + fs);
        CP16(buf + (2+L)*TILE_B + tid*ROWB + 16, GF[L] + fs + 8);
    }
}

__global__ __launch_bounds__(128, 2)
void conv_mma_kernel(const float* __restrict__ bias) {
    extern __shared__ char smem[];
    uint32_t sb = smem_u32(smem);
    const int tid = threadIdx.x, lane = tid & 31, w = tid >> 5;
    const int wo = w & 1, wl = w >> 1;      // warp covers o: wo*64, l: wl*64
    const int b = blockIdx.z, o0 = blockIdx.y*128, l0 = blockIdx.x*128;

    float acc[4][8][4];
#pragma unroll
    for (int i=0;i<4;i++)
#pragma unroll
        for (int j=0;j<8;j++)
#pragma unroll
            for (int k=0;k<4;k++) acc[i][j][k]=0.f;

    load_stage(sb, 0, b, l0, o0, tid); CPCOMMIT();
    load_stage(sb, 1, b, l0, o0, tid); CPCOMMIT();
    load_stage(sb, 2, b, l0, o0, tid); CPCOMMIT();

    const int lr = lane & 15, lc16 = (lane >> 4) * 16;

    for (int s = 0; s < 96; s++) {
        CPWAIT2();
        __syncthreads();
        const uint32_t buf = sb + (uint32_t)(s & 3)*STG_B;
        uint32_t a1[4][4], a2[4][4], b1[4][4], b2[4][4];
#pragma unroll
        for (int mt = 0; mt < 4; mt++) {
            uint32_t r = (uint32_t)(wo*64 + mt*16 + lr)*ROWB + lc16;
            LDSM4(a1[mt], buf + 0*TILE_B + r);
            LDSM4(a2[mt], buf + 1*TILE_B + r);
        }
#pragma unroll
        for (int nt = 0; nt < 4; nt++) {
            uint32_t r = (uint32_t)(wl*64 + nt*16 + lr)*ROWB + lc16;
            LDSM4(b1[nt], buf + 2*TILE_B + r);
            LDSM4(b2[nt], buf + 3*TILE_B + r);
        }
#define COMBO(A,B) \
        _Pragma("unroll") \
        for (int mt = 0; mt < 4; mt++) \
        _Pragma("unroll") \
        for (int nt = 0; nt < 4; nt++) { \
            MMA(acc[mt][2*nt],   A[mt], B[nt][0], B[nt][2]); \
            MMA(acc[mt][2*nt+1], A[mt], B[nt][1], B[nt][3]); \
        }
        COMBO(a1,b1) COMBO(a1,b2) COMBO(a2,b1)
#undef COMBO
        __syncthreads();
        if (s + 3 < 96) { load_stage(sb, s+3, b, l0, o0, tid); }
        CPCOMMIT();
    }

    // epilogue: bias + relu -> h[b][o][l]
    const int r0 = lane >> 2, cp = (lane & 3)*2;
    float* hb = g_h + (size_t)b*NC*NL;
#pragma unroll
    for (int mt = 0; mt < 4; mt++) {
        int o_ = o0 + wo*64 + mt*16 + r0;
        float bv0 = __ldg(bias + o_), bv1 = __ldg(bias + o_ + 8);
#pragma unroll
        for (int nb = 0; nb < 8; nb++) {
            int lc = l0 + wl*64 + nb*8 + cp;
            float2 v0 = make_float2(fmaxf(acc[mt][nb][0]+bv0, 0.f),
                                    fmaxf(acc[mt][nb][1]+bv0, 0.f));
            float2 v1 = make_float2(fmaxf(acc[mt][nb][2]+bv1, 0.f),
                                    fmaxf(acc[mt][nb][3]+bv1, 0.f));
            *(float2*)(hb + (size_t)o_*NL + lc) = v0;
            *(float2*)(hb + (size_t)(o_+8)*NL + lc) = v1;
        }
    }
}

// ---- heads + decode + scores ----
__global__ __launch_bounds__(256)
void proj_kernel(const float* __restrict__ obj_w, const float* __restrict__ obj_b,
                 const float* __restrict__ reg_w, const float* __restrict__ reg_b,
                 float* __restrict__ out) {
    __shared__ float ws[21*512];
    const int b = blockIdx.y, l0 = blockIdx.x*512, tid = threadIdx.x;
    for (int i = tid; i < 7*512;  i += 256) ws[i] = obj_w[i];
    for (int i = tid; i < 14*512; i += 256) ws[3584 + i] = reg_w[i];
    __syncthreads();
    float acc[21][2];
#pragma unroll
    for (int a = 0; a < 21; a++) { acc[a][0]=0.f; acc[a][1]=0.f; }
    const float* hb = g_h + (size_t)b*NC*NL + l0 + tid;
#pragma unroll 4
    for (int c = 0; c < NC; c++) {
        float h0 = hb[(size_t)c*NL], h1 = hb[(size_t)c*NL + 256];
#pragma unroll
        for (int a = 0; a < 21; a++) {
            float wv = ws[a*512 + c];
            acc[a][0] += wv*h0; acc[a][1] += wv*h1;
        }
    }
#pragma unroll
    for (int r = 0; r < 2; r++) {
        int l = l0 + 256*r + tid;
#pragma unroll
        for (int a = 0; a < NA; a++) {
            float ol = acc[a][r] + __ldg(obj_b + a);
            size_t n = (size_t)b*NPA + (size_t)l*NA + a;
            out[OFF_OBJ + n] = ol;
            g_scores[n] = 1.f/(1.f + expf(-ol));
            float tc = acc[7+2*a][r] + __ldg(reg_b + 2*a);
            float tw = acc[7+2*a+1][r] + __ldg(reg_b + 2*a+1);
            out[OFF_REG + 2*n] = tc; out[OFF_REG + 2*n+1] = tw;
            float len = c_lens[a];
            float twc = fminf(fmaxf(tw, -10.f), 10.f);
            float cc = ((float)l + 0.5f) + tc*len;
            float ww = len * expf(twc);
            float s = fminf(fmaxf(cc - 0.5f*ww, 0.f), 8192.f);
            float e = fminf(fmaxf(cc + 0.5f*ww, 0.f), 8192.f);
            e = fminf(fmaxf(e, s + 1e-3f), 8192.f);
            s = fmaxf(fminf(s, e - 1e-3f), 0.f);
            g_boxes[2*n] = s; g_boxes[2*n+1] = e;
        }
    }
}

__global__ void anchors_kernel(float* __restrict__ out) {
    int n = blockIdx.x*blockDim.x + threadIdx.x;
    if (n < NPA) {
        int l = n / NA, a = n % NA;
        float cen = (float)l + 0.5f, half = 0.5f*c_lens[a];
        out[OFF_ANCH + 2*n] = cen - half;
        out[OFF_ANCH + 2*n + 1] = cen + half;
    }
}

// ---- topk + NMS ----
#define TK_SMEM 65536
__global__ __launch_bounds__(512)
void topk_nms_kernel(float* __restrict__ out) {
    extern __shared__ char dynsm[];
    int* hist = (int*)dynsm;
    unsigned long long* keys = (unsigned long long*)dynsm;
    unsigned* smask = (unsigned*)(dynsm + 8192);
    int* eqbuf = (int*)(dynsm + 57344);
    __shared__ float sbox[PRE_K*2];
    __shared__ float ssc[PRE_K];
    __shared__ int skept[POST_K];
    __shared__ int csum[512];
    __shared__ int s_cnt, s_g, s_e, s_nk, s_B, s_ncand;

    const int b = blockIdx.x, tid = threadIdx.x;
    const float* sc = g_scores + (size_t)b*NPA;

    for (int i = tid; i < 16384; i += 512) hist[i] = 0;
    __syncthreads();
    for (int p = tid; p < NPA; p += 512)
        atomicAdd(&hist[__float_as_uint(sc[p]) >> 16], 1);
    __syncthreads();
    int cs = 0;
#pragma unroll 8
    for (int j = 0; j < 32; j++) cs += hist[tid*32 + j];
    csum[tid] = cs;
    __syncthreads();
    if (tid == 0) {
        int acc = 0, tc = 511;
        for (; tc > 0; tc--) { if (acc + csum[tc] >= PRE_K) break; acc += csum[tc]; }
        int B = tc*32;
        for (int j = tc*32 + 31; j >= tc*32; j--) {
            if (acc + hist[j] >= PRE_K) { B = j; break; }
            acc += hist[j];
        }
        s_B = B; s_ncand = acc + hist[B];
    }
    __syncthreads();
    const int B = s_B;
    const int ncand = s_ncand;

    if (ncand <= 1024) {
        if (tid == 0) s_g = 0;
        __syncthreads();
        for (int p = tid; p < NPA; p += 512) {
            unsigned bits = __float_as_uint(sc[p]);
            if ((int)(bits >> 16) >= B) {
                int q = atomicAdd(&s_g, 1);
                keys[q] = ((unsigned long long)bits << 32) |
                          (unsigned long long)(0xFFFFFFFFu - (unsigned)p);
            }
        }
        __syncthreads();
        for (int i = tid + ncand; i < 1024; i += 512) keys[i] = 0ULL;
    } else {
        unsigned lo = (unsigned)B << 16, hi = ((unsigned)B << 16) + 0x10000u;
        for (int it = 0; it < 17 && (hi - lo) > 1u; ++it) {
            unsigned mid = lo + ((hi - lo) >> 1);
            if (tid == 0) s_cnt = 0;
            __syncthreads();
            int c = 0;
            for (int p = tid; p < NPA; p += 512)
                c += (__float_as_uint(sc[p]) >= mid) ? 1 : 0;
#pragma unroll
            for (int o = 16; o; o >>= 1) c += __shfl_down_sync(0xffffffffu, c, o);
            if ((tid & 31) == 0) atomicAdd(&s_cnt, c);
            __syncthreads();
            if (s_cnt >= PRE_K) lo = mid; else hi = mid;
            __syncthreads();
        }
        unsigned V = lo;
        if (tid == 0) { s_g = 0; s_e = 0; }
        __syncthreads();
        for (int p = tid; p < NPA; p += 512) {
            unsigned bits = __float_as_uint(sc[p]);
            if (bits > V) {
                int q = atomicAdd(&s_g, 1);
                if (q < 1024)
                    keys[q] = ((unsigned long long)bits << 32) |
                              (unsigned long long)(0xFFFFFFFFu - (unsigned)p);
            } else if (bits == V) {
                int q = atomicAdd(&s_e, 1);
                if (q < 1024) eqbuf[q] = p;
            }
        }
        __syncthreads();
        int ng = s_g < 1024 ? s_g : 1024;
        int ne = s_e < 1024 ? s_e : 1024;
        for (int i = tid; i < 1024; i += 512) {
            if (i >= ng) {
                int e = i - ng;
                keys[i] = (e < ne)
                    ? (((unsigned long long)V << 32) |
                       (unsigned long long)(0xFFFFFFFFu - (unsigned)eqbuf[e]))
                    : 0ULL;
            }
        }
    }

    for (int k = 2; k <= 1024; k <<= 1)
        for (int j = k >> 1; j > 0; j >>= 1) {
            __syncthreads();
            for (int i = tid; i < 1024; i += 512) {
                int l = i ^ j;
                if (l > i) {
                    unsigned long long a = keys[i], bb = keys[l];
                    bool up = ((i & k) == 0);
                    if (up ? (a < bb) : (a > bb)) { keys[i] = bb; keys[l] = a; }
                }
            }
        }
    __syncthreads();

    for (int i = tid; i < PRE_K; i += 512) {
        unsigned long long kv = keys[i];
        unsigned bits = (unsigned)(kv >> 32);
        if (bits == 0u) { ssc[i] = 0.f; sbox[2*i] = 0.f; sbox[2*i+1] = 0.f; }
        else {
            unsigned ridx = 0xFFFFFFFFu - (unsigned)(kv & 0xFFFFFFFFull);
            ssc[i] = __uint_as_float(bits);
            const float* bp = g_boxes + ((size_t)b*NPA + ridx)*2;
            sbox[2*i] = bp[0]; sbox[2*i+1] = bp[1];
        }
    }
    __syncthreads();

    for (int i = tid; i < PRE_K; i += 512) {
        float si = sbox[2*i], ei = sbox[2*i+1], wi = ei - si;
        for (int w = 0; w < NMW; w++) {
            unsigned m = 0;
            int jb = w*32, jm = i - jb; if (jm > 32) jm = 32;
            for (int jj = 0; jj < jm; jj++) {
                int j = jb + jj;
                float sj = sbox[2*j], ej = sbox[2*j+1];
                float inter = fmaxf(fminf(ei, ej) - fmaxf(si, sj), 0.f);
                float iou = inter / fmaxf(wi + (ej - sj) - inter, 1e-6f);
                if (iou > 0.5f) m |= (1u << jj);
            }
            smask[i*NMW + w] = m;
        }
    }
    __syncthreads();

    if (tid < 32) {
        int lane = tid;
        unsigned keepw = 0;
        int nk = 0;
        for (int i = 0; i < PRE_K; i++) {
            unsigned mw = (lane < NMW) ? smask[i*NMW + lane] : 0u;
            bool sup = __any_sync(0xffffffffu, (mw & keepw) != 0u);
            bool val = (ssc[i] >= 0.1f);
            if (val && !sup) {
                if (lane == (i >> 5)) keepw |= (1u << (i & 31));
                if (lane == 0 && nk < POST_K) skept[nk] = i;
                nk++;
            }
        }
        if (lane == 0) s_nk = (nk < POST_K) ? nk : POST_K;
    }
    __syncthreads();

    int nk = s_nk;
    for (int r = tid; r < POST_K; r += 512) {
        bool on = r < nk;
        int i = on ? skept[r] : 0;
        size_t base = (size_t)b*POST_K + r;
        out[OFF_PROPS + 2*base]   = on ? sbox[2*i]   : 0.f;
        out[OFF_PROPS + 2*base+1] = on ? sbox[2*i+1] : 0.f;
        out[OFF_PSC + base]   = on ? ssc[i] : 0.f;
        out[OFF_PMASK + base] = on ? 1.0f : 0.0f;
    }
}

// ---------------------------------------------------------------------------
extern "C" void kernel_launch(void* const* d_in, const int* in_sizes, int n_in,
                              void* d_out, int out_size) {
    const float* feat   = (const float*)d_in[0];
    const float* conv_w = (const float*)d_in[1];
    const float* conv_b = (const float*)d_in[2];
    const float* obj_w  = (const float*)d_in[3];
    const float* obj_b  = (const float*)d_in[4];
    const float* reg_w  = (const float*)d_in[5];
    const float* reg_b  = (const float*)d_in[6];
    float* out = (float*)d_out;

    cudaFuncSetAttribute(conv_mma_kernel, cudaFuncAttributeMaxDynamicSharedMemorySize, CONV_SMEM);
    cudaFuncSetAttribute(topk_nms_kernel, cudaFuncAttributeMaxDynamicSharedMemorySize, TK_SMEM);

    splitw_kernel<<<(3*512*512 + 255)/256, 256>>>(conv_w);
    pad_kernel<<<NB, 512>>>();
    dim3 sgrid(NL/64, NC/64, NB);
    splitfeat_kernel<<<sgrid, 256>>>(feat);

    dim3 cgrid(NL/128, NC/128, NB);          // (64, 4, 8)
    conv_mma_kernel<<<cgrid, 128, CONV_SMEM>>>(conv_b);

    dim3 pgrid(NL/512, NB);
    proj_kernel<<<pgrid, 256>>>(obj_w, obj_b, reg_w, reg_b, out);

    anchors_kernel<<<(NPA + 255)/256, 256>>>(out);

    topk_nms_kernel<<<NB, 512, TK_SMEM>>>(out);
}

// round 8
// speedup vs baseline: 1.0711x; 1.0711x over previous
#include <cuda_runtime.h>
#include <cuda_fp16.h>
#include <math.h>
#include <stdint.h>

#define NB 8
#define NC 512
#define NL 8192
#define NA 7
#define NPA (NL*NA)
#define PRE_K 600
#define POST_K 100
#define NMW 19
#define LPAD 8194

#define OFF_OBJ  0
#define SZ_OBJ   (NB*NPA)
#define OFF_REG  (SZ_OBJ)
#define SZ_REG   (NB*NPA*2)
#define OFF_ANCH (OFF_REG + SZ_REG)
#define SZ_ANCH  (NPA*2)
#define OFF_PROPS (OFF_ANCH + SZ_ANCH)
#define SZ_PROPS (NB*POST_K*2)
#define OFF_PSC  (OFF_PROPS + SZ_PROPS)
#define OFF_PMASK (OFF_PSC + NB*POST_K)

__device__ float g_h[(size_t)NB*NC*NL];
__device__ float g_boxes[(size_t)NB*NPA*2];
__device__ float g_scores[(size_t)NB*NPA];
__device__ __align__(256) __half g_fT1[(size_t)NB*LPAD*NC];
__device__ __align__(256) __half g_fT2[(size_t)NB*LPAD*NC];
__device__ __align__(256) __half g_W1[3*512*512];
__device__ __align__(256) __half g_W2[3*512*512];

__constant__ float c_lens[NA] = {1.f,2.f,3.f,4.f,5.f,7.f,9.f};

__device__ __forceinline__ uint32_t smem_u32(const void* p) {
    uint32_t a;
    asm("{ .reg .u64 t; cvta.to.shared.u64 t, %1; cvt.u32.u64 %0, t; }" : "=r"(a) : "l"(p));
    return a;
}
#define CP16(dst,src) asm volatile("cp.async.cg.shared.global [%0], [%1], 16;"::"r"(dst),"l"(src))
#define CPCOMMIT() asm volatile("cp.async.commit_group;":::"memory")
#define CPWAIT1() asm volatile("cp.async.wait_group 1;":::"memory")
#define LDSM4(r,addr) asm volatile( \
    "ldmatrix.sync.aligned.m8n8.x4.shared.b16 {%0,%1,%2,%3}, [%4];" \
    : "=r"((r)[0]),"=r"((r)[1]),"=r"((r)[2]),"=r"((r)[3]) : "r"(addr))
#define MMA(d,a,b0,b1) asm volatile( \
    "mma.sync.aligned.m16n8k16.row.col.f32.f16.f16.f32 " \
    "{%0,%1,%2,%3}, {%4,%5,%6,%7}, {%8,%9}, {%0,%1,%2,%3};" \
    : "+f"((d)[0]),"+f"((d)[1]),"+f"((d)[2]),"+f"((d)[3]) \
    : "r"((a)[0]),"r"((a)[1]),"r"((a)[2]),"r"((a)[3]),"r"(b0),"r"(b1))

// ---- prep: 2-limb fp16 splits ----
__global__ void splitw_kernel(const float* __restrict__ w) {
    int idx = blockIdx.x*256 + threadIdx.x;
    if (idx >= 3*512*512) return;
    int c = idx & 511, o = (idx >> 9) & 511, t = idx >> 18;
    float v = w[(size_t)o*1536 + c*3 + t];
    __half a1 = __float2half_rn(v);
    g_W1[idx] = a1;
    g_W2[idx] = __float2half_rn(v - __half2float(a1));
}
__global__ void pad_kernel() {
    int b = blockIdx.x, c = threadIdx.x;
    __half z = __float2half_rn(0.f);
    size_t r0 = ((size_t)b*LPAD)*NC + c, r1 = ((size_t)b*LPAD + (LPAD-1))*NC + c;
    g_fT1[r0]=z; g_fT2[r0]=z;
    g_fT1[r1]=z; g_fT2[r1]=z;
}
__global__ __launch_bounds__(256)
void splitfeat_kernel(const float* __restrict__ feat) {
    __shared__ float tile[64][65];
    int b = blockIdx.z, c0 = blockIdx.y*64, l0 = blockIdx.x*64;
    int tj = threadIdx.x & 63, ti = threadIdx.x >> 6;
    const float* src = feat + ((size_t)b*NC + c0)*NL + l0;
#pragma unroll
    for (int i = ti; i < 64; i += 4) tile[i][tj] = src[(size_t)i*NL + tj];
    __syncthreads();
#pragma unroll
    for (int lj = ti; lj < 64; lj += 4) {
        float v = tile[tj][lj];
        __half a1 = __float2half_rn(v);
        size_t dst = ((size_t)b*LPAD + (l0 + lj + 1))*NC + c0 + tj;
        g_fT1[dst] = a1;
        g_fT2[dst] = __float2half_rn(v - __half2float(a1));
    }
}

// ---- conv: CTA 128(o) x 128(l); 32 c-chunks of k=16, taps share F window ----
#define ROWB   48u
#define WTILE_B 6144u               // 128 rows * 48B
#define F_OFF   36864u              // 6 W tiles
#define FTILE_B 6336u               // 132 rows * 48B
#define STG_B   49664u              // 49536 used, 128-aligned
#define CONV_SMEM (3u*STG_B)        // 148992 B, 1 CTA/SM

__device__ __forceinline__ void load_stage(uint32_t sb, int s,
                                           int b, int l0, int o0, int tid) {
    const uint32_t buf = sb + (uint32_t)(s % 3)*STG_B;
    const int c0 = s << 4;
    // W: 6 tiles (t,L) x 128 rows, 32B per row-task -> 768 tasks
#pragma unroll
    for (int i = 0; i < 3; i++) {
        int idx = tid + 256*i;
        int r = idx & 127, tl = idx >> 7;       // tl = t*2+L, 0..5
        const __half* gw = (tl & 1) ? g_W2 : g_W1;
        size_t src = ((size_t)((tl>>1)*512 + o0 + r))*512 + c0;
        uint32_t dst = buf + (uint32_t)tl*WTILE_B + (uint32_t)r*ROWB;
        CP16(dst, gw + src); CP16(dst + 16, gw + src + 8);
    }
    // F: 2 limbs x 130 rows (fT rows l0..l0+129) -> 260 tasks
#pragma unroll
    for (int i = 0; i < 2; i++) {
        int idx = tid + 256*i;
        if (idx < 260) {
            int fr = idx % 130, L = idx / 130;
            const __half* gf = L ? g_fT2 : g_fT1;
            size_t src = ((size_t)b*LPAD + (size_t)(l0 + fr))*512 + c0;
            uint32_t dst = buf + F_OFF + (uint32_t)L*FTILE_B + (uint32_t)fr*ROWB;
            CP16(dst, gf + src); CP16(dst + 16, gf + src + 8);
        }
    }
}

__global__ __launch_bounds__(256, 1)
void conv_mma_kernel(const float* __restrict__ bias) {
    extern __shared__ char smem[];
    uint32_t sb = smem_u32(smem);
    const int tid = threadIdx.x, lane = tid & 31, w = tid >> 5;
    const int wo = w & 1, wl = w >> 1;           // warp: o 64-half, l 32-quarter
    const int b = blockIdx.z, o0 = blockIdx.y*128, l0 = blockIdx.x*128;

    float acc[4][4][4];
#pragma unroll
    for (int i=0;i<4;i++)
#pragma unroll
        for (int j=0;j<4;j++)
#pragma unroll
            for (int k=0;k<4;k++) acc[i][j][k]=0.f;

    load_stage(sb, 0, b, l0, o0, tid); CPCOMMIT();
    load_stage(sb, 1, b, l0, o0, tid); CPCOMMIT();

    const int lr = lane & 15, lc16 = (lane >> 4) * 16;

    for (int s = 0; s < 32; s++) {
        CPWAIT1();
        __syncthreads();
        const uint32_t buf = sb + (uint32_t)(s % 3)*STG_B;
#pragma unroll
        for (int t = 0; t < 3; t++) {
            const uint32_t wbase = buf + (uint32_t)(t*2)*WTILE_B;
            uint32_t a1[4][4], a2[4][4], b1[2][4], b2[2][4];
#pragma unroll
            for (int mt = 0; mt < 4; mt++) {
                uint32_t r = (uint32_t)(wo*64 + mt*16 + lr)*ROWB + lc16;
                LDSM4(a1[mt], wbase + r);
                LDSM4(a2[mt], wbase + WTILE_B + r);
            }
#pragma unroll
            for (int nt = 0; nt < 2; nt++) {
                uint32_t r = (uint32_t)(wl*32 + nt*16 + lr + t)*ROWB + lc16;
                LDSM4(b1[nt], buf + F_OFF + r);
                LDSM4(b2[nt], buf + F_OFF + FTILE_B + r);
            }
#define COMBO(A,B) \
            _Pragma("unroll") \
            for (int mt = 0; mt < 4; mt++) \
            _Pragma("unroll") \
            for (int nt = 0; nt < 2; nt++) { \
                MMA(acc[mt][2*nt],   A[mt], B[nt][0], B[nt][2]); \
                MMA(acc[mt][2*nt+1], A[mt], B[nt][1], B[nt][3]); \
            }
            COMBO(a1,b1) COMBO(a1,b2) COMBO(a2,b1)
#undef COMBO
        }
        if (s + 2 < 32) { load_stage(sb, s+2, b, l0, o0, tid); }
        CPCOMMIT();
    }

    // epilogue: bias + relu -> h[b][o][l]
    const int r0 = lane >> 2, cp = (lane & 3)*2;
    float* hb = g_h + (size_t)b*NC*NL;
#pragma unroll
    for (int mt = 0; mt < 4; mt++) {
        int o_ = o0 + wo*64 + mt*16 + r0;
        float bv0 = __ldg(bias + o_), bv1 = __ldg(bias + o_ + 8);
#pragma unroll
        for (int nb = 0; nb < 4; nb++) {
            int lc = l0 + wl*32 + nb*8 + cp;
            float2 v0 = make_float2(fmaxf(acc[mt][nb][0]+bv0, 0.f),
                                    fmaxf(acc[mt][nb][1]+bv0, 0.f));
            float2 v1 = make_float2(fmaxf(acc[mt][nb][2]+bv1, 0.f),
                                    fmaxf(acc[mt][nb][3]+bv1, 0.f));
            *(float2*)(hb + (size_t)o_*NL + lc) = v0;
            *(float2*)(hb + (size_t)(o_+8)*NL + lc) = v1;
        }
    }
}

// ---- heads + decode + scores ----
__global__ __launch_bounds__(256)
void proj_kernel(const float* __restrict__ obj_w, const float* __restrict__ obj_b,
                 const float* __restrict__ reg_w, const float* __restrict__ reg_b,
                 float* __restrict__ out) {
    __shared__ float ws[21*512];
    const int b = blockIdx.y, l0 = blockIdx.x*512, tid = threadIdx.x;
    for (int i = tid; i < 7*512;  i += 256) ws[i] = obj_w[i];
    for (int i = tid; i < 14*512; i += 256) ws[3584 + i] = reg_w[i];
    __syncthreads();
    float acc[21][2];
#pragma unroll
    for (int a = 0; a < 21; a++) { acc[a][0]=0.f; acc[a][1]=0.f; }
    const float* hb = g_h + (size_t)b*NC*NL + l0 + tid;
#pragma unroll 4
    for (int c = 0; c < NC; c++) {
        float h0 = hb[(size_t)c*NL], h1 = hb[(size_t)c*NL + 256];
#pragma unroll
        for (int a = 0; a < 21; a++) {
            float wv = ws[a*512 + c];
            acc[a][0] += wv*h0; acc[a][1] += wv*h1;
        }
    }
#pragma unroll
    for (int r = 0; r < 2; r++) {
        int l = l0 + 256*r + tid;
#pragma unroll
        for (int a = 0; a < NA; a++) {
            float ol = acc[a][r] + __ldg(obj_b + a);
            size_t n = (size_t)b*NPA + (size_t)l*NA + a;
            out[OFF_OBJ + n] = ol;
            g_scores[n] = 1.f/(1.f + expf(-ol));
            float tc = acc[7+2*a][r] + __ldg(reg_b + 2*a);
            float tw = acc[7+2*a+1][r] + __ldg(reg_b + 2*a+1);
            out[OFF_REG + 2*n] = tc; out[OFF_REG + 2*n+1] = tw;
            float len = c_lens[a];
            float twc = fminf(fmaxf(tw, -10.f), 10.f);
            float cc = ((float)l + 0.5f) + tc*len;
            float ww = len * expf(twc);
            float s = fminf(fmaxf(cc - 0.5f*ww, 0.f), 8192.f);
            float e = fminf(fmaxf(cc + 0.5f*ww, 0.f), 8192.f);
            e = fminf(fmaxf(e, s + 1e-3f), 8192.f);
            s = fmaxf(fminf(s, e - 1e-3f), 0.f);
            g_boxes[2*n] = s; g_boxes[2*n+1] = e;
        }
    }
}

__global__ void anchors_kernel(float* __restrict__ out) {
    int n = blockIdx.x*blockDim.x + threadIdx.x;
    if (n < NPA) {
        int l = n / NA, a = n % NA;
        float cen = (float)l + 0.5f, half = 0.5f*c_lens[a];
        out[OFF_ANCH + 2*n] = cen - half;
        out[OFF_ANCH + 2*n + 1] = cen + half;
    }
}

// ---- topk + NMS ----
#define TK_SMEM 65536
__global__ __launch_bounds__(512)
void topk_nms_kernel(float* __restrict__ out) {
    extern __shared__ char dynsm[];
    int* hist = (int*)dynsm;
    unsigned long long* keys = (unsigned long long*)dynsm;
    unsigned* smask = (unsigned*)(dynsm + 8192);
    int* eqbuf = (int*)(dynsm + 57344);
    __shared__ float sbox[PRE_K*2];
    __shared__ float ssc[PRE_K];
    __shared__ int skept[POST_K];
    __shared__ int csum[512];
    __shared__ int s_cnt, s_g, s_e, s_nk, s_B, s_ncand;

    const int b = blockIdx.x, tid = threadIdx.x;
    const float* sc = g_scores + (size_t)b*NPA;

    for (int i = tid; i < 16384; i += 512) hist[i] = 0;
    __syncthreads();
    for (int p = tid; p < NPA; p += 512)
        atomicAdd(&hist[__float_as_uint(sc[p]) >> 16], 1);
    __syncthreads();
    int cs = 0;
#pragma unroll 8
    for (int j = 0; j < 32; j++) cs += hist[tid*32 + j];
    csum[tid] = cs;
    __syncthreads();
    if (tid == 0) {
        int acc = 0, tc = 511;
        for (; tc > 0; tc--) { if (acc + csum[tc] >= PRE_K) break; acc += csum[tc]; }
        int B = tc*32;
        for (int j = tc*32 + 31; j >= tc*32; j--) {
            if (acc + hist[j] >= PRE_K) { B = j; break; }
            acc += hist[j];
        }
        s_B = B; s_ncand = acc + hist[B];
    }
    __syncthreads();
    const int B = s_B;
    const int ncand = s_ncand;

    if (ncand <= 1024) {
        if (tid == 0) s_g = 0;
        __syncthreads();
        for (int p = tid; p < NPA; p += 512) {
            unsigned bits = __float_as_uint(sc[p]);
            if ((int)(bits >> 16) >= B) {
                int q = atomicAdd(&s_g, 1);
                keys[q] = ((unsigned long long)bits << 32) |
                          (unsigned long long)(0xFFFFFFFFu - (unsigned)p);
            }
        }
        __syncthreads();
        for (int i = tid + ncand; i < 1024; i += 512) keys[i] = 0ULL;
    } else {
        unsigned lo = (unsigned)B << 16, hi = ((unsigned)B << 16) + 0x10000u;
        for (int it = 0; it < 17 && (hi - lo) > 1u; ++it) {
            unsigned mid = lo + ((hi - lo) >> 1);
            if (tid == 0) s_cnt = 0;
            __syncthreads();
            int c = 0;
            for (int p = tid; p < NPA; p += 512)
                c += (__float_as_uint(sc[p]) >= mid) ? 1 : 0;
#pragma unroll
            for (int o = 16; o; o >>= 1) c += __shfl_down_sync(0xffffffffu, c, o);
            if ((tid & 31) == 0) atomicAdd(&s_cnt, c);
            __syncthreads();
            if (s_cnt >= PRE_K) lo = mid; else hi = mid;
            __syncthreads();
        }
        unsigned V = lo;
        if (tid == 0) { s_g = 0; s_e = 0; }
        __syncthreads();
        for (int p = tid; p < NPA; p += 512) {
            unsigned bits = __float_as_uint(sc[p]);
            if (bits > V) {
                int q = atomicAdd(&s_g, 1);
                if (q < 1024)
                    keys[q] = ((unsigned long long)bits << 32) |
                              (unsigned long long)(0xFFFFFFFFu - (unsigned)p);
            } else if (bits == V) {
                int q = atomicAdd(&s_e, 1);
                if (q < 1024) eqbuf[q] = p;
            }
        }
        __syncthreads();
        int ng = s_g < 1024 ? s_g : 1024;
        int ne = s_e < 1024 ? s_e : 1024;
        for (int i = tid; i < 1024; i += 512) {
            if (i >= ng) {
                int e = i - ng;
                keys[i] = (e < ne)
                    ? (((unsigned long long)V << 32) |
                       (unsigned long long)(0xFFFFFFFFu - (unsigned)eqbuf[e]))
                    : 0ULL;
            }
        }
    }

    for (int k = 2; k <= 1024; k <<= 1)
        for (int j = k >> 1; j > 0; j >>= 1) {
            __syncthreads();
            for (int i = tid; i < 1024; i += 512) {
                int l = i ^ j;
                if (l > i) {
                    unsigned long long a = keys[i], bb = keys[l];
                    bool up = ((i & k) == 0);
                    if (up ? (a < bb) : (a > bb)) { keys[i] = bb; keys[l] = a; }
                }
            }
        }
    __syncthreads();

    for (int i = tid; i < PRE_K; i += 512) {
        unsigned long long kv = keys[i];
        unsigned bits = (unsigned)(kv >> 32);
        if (bits == 0u) { ssc[i] = 0.f; sbox[2*i] = 0.f; sbox[2*i+1] = 0.f; }
        else {
            unsigned ridx = 0xFFFFFFFFu - (unsigned)(kv & 0xFFFFFFFFull);
            ssc[i] = __uint_as_float(bits);
            const float* bp = g_boxes + ((size_t)b*NPA + ridx)*2;
            sbox[2*i] = bp[0]; sbox[2*i+1] = bp[1];
        }
    }
    __syncthreads();

    for (int i = tid; i < PRE_K; i += 512) {
        float si = sbox[2*i], ei = sbox[2*i+1], wi = ei - si;
        for (int w = 0; w < NMW; w++) {
            unsigned m = 0;
            int jb = w*32, jm = i - jb; if (jm > 32) jm = 32;
            for (int jj = 0; jj < jm; jj++) {
                int j = jb + jj;
                float sj = sbox[2*j], ej = sbox[2*j+1];
                float inter = fmaxf(fminf(ei, ej) - fmaxf(si, sj), 0.f);
                float iou = inter / fmaxf(wi + (ej - sj) - inter, 1e-6f);
                if (iou > 0.5f) m |= (1u << jj);
            }
            smask[i*NMW + w] = m;
        }
    }
    __syncthreads();

    if (tid < 32) {
        int lane = tid;
        unsigned keepw = 0;
        int nk = 0;
        for (int i = 0; i < PRE_K; i++) {
            unsigned mw = (lane < NMW) ? smask[i*NMW + lane] : 0u;
            bool sup = __any_sync(0xffffffffu, (mw & keepw) != 0u);
            bool val = (ssc[i] >= 0.1f);
            if (val && !sup) {
                if (lane == (i >> 5)) keepw |= (1u << (i & 31));
                if (lane == 0 && nk < POST_K) skept[nk] = i;
                nk++;
            }
        }
        if (lane == 0) s_nk = (nk < POST_K) ? nk : POST_K;
    }
    __syncthreads();

    int nk = s_nk;
    for (int r = tid; r < POST_K; r += 512) {
        bool on = r < nk;
        int i = on ? skept[r] : 0;
        size_t base = (size_t)b*POST_K + r;
        out[OFF_PROPS + 2*base]   = on ? sbox[2*i]   : 0.f;
        out[OFF_PROPS + 2*base+1] = on ? sbox[2*i+1] : 0.f;
        out[OFF_PSC + base]   = on ? ssc[i] : 0.f;
        out[OFF_PMASK + base] = on ? 1.0f : 0.0f;
    }
}

// ---------------------------------------------------------------------------
extern "C" void kernel_launch(void* const* d_in, const int* in_sizes, int n_in,
                              void* d_out, int out_size) {
    const float* feat   = (const float*)d_in[0];
    const float* conv_w = (const float*)d_in[1];
    const float* conv_b = (const float*)d_in[2];
    const float* obj_w  = (const float*)d_in[3];
    const float* obj_b  = (const float*)d_in[4];
    const float* reg_w  = (const float*)d_in[5];
    const float* reg_b  = (const float*)d_in[6];
    float* out = (float*)d_out;

    cudaFuncSetAttribute(conv_mma_kernel, cudaFuncAttributeMaxDynamicSharedMemorySize, CONV_SMEM);
    cudaFuncSetAttribute(topk_nms_kernel, cudaFuncAttributeMaxDynamicSharedMemorySize, TK_SMEM);

    splitw_kernel<<<(3*512*512 + 255)/256, 256>>>(conv_w);
    pad_kernel<<<NB, 512>>>();
    dim3 sgrid(NL/64, NC/64, NB);
    splitfeat_kernel<<<sgrid, 256>>>(feat);

    dim3 cgrid(NL/128, NC/128, NB);          // (64, 4, 8)
    conv_mma_kernel<<<cgrid, 256, CONV_SMEM>>>(conv_b);

    dim3 pgrid(NL/512, NB);
    proj_kernel<<<pgrid, 256>>>(obj_w, obj_b, reg_w, reg_b, out);

    anchors_kernel<<<(NPA + 255)/256, 256>>>(out);

    topk_nms_kernel<<<NB, 512, TK_SMEM>>>(out);
}

// round 9
// speedup vs baseline: 1.0979x; 1.0250x over previous
#include <cuda_runtime.h>
#include <cuda_fp16.h>
#include <math.h>
#include <stdint.h>

#define NB 8
#define NC 512
#define NL 8192
#define NA 7
#define NPA (NL*NA)
#define PRE_K 600
#define POST_K 100
#define NMW 19
#define LPAD 8194

#define OFF_OBJ  0
#define SZ_OBJ   (NB*NPA)
#define OFF_REG  (SZ_OBJ)
#define SZ_REG   (NB*NPA*2)
#define OFF_ANCH (OFF_REG + SZ_REG)
#define SZ_ANCH  (NPA*2)
#define OFF_PROPS (OFF_ANCH + SZ_ANCH)
#define SZ_PROPS (NB*POST_K*2)
#define OFF_PSC  (OFF_PROPS + SZ_PROPS)
#define OFF_PMASK (OFF_PSC + NB*POST_K)

__device__ float g_h[(size_t)NB*NC*NL];
__device__ float g_boxes[(size_t)NB*NPA*2];
__device__ float g_scores[(size_t)NB*NPA];
__device__ __align__(256) __half g_fT1[(size_t)NB*LPAD*NC];
__device__ __align__(256) __half g_fT2[(size_t)NB*LPAD*NC];
__device__ __align__(256) __half g_W1[3*512*512];
__device__ __align__(256) __half g_W2[3*512*512];

__constant__ float c_lens[NA] = {1.f,2.f,3.f,4.f,5.f,7.f,9.f};

__device__ __forceinline__ uint32_t smem_u32(const void* p) {
    uint32_t a;
    asm("{ .reg .u64 t; cvta.to.shared.u64 t, %1; cvt.u32.u64 %0, t; }" : "=r"(a) : "l"(p));
    return a;
}
#define CP16(dst,src) asm volatile("cp.async.cg.shared.global [%0], [%1], 16;"::"r"(dst),"l"(src))
#define CPCOMMIT() asm volatile("cp.async.commit_group;":::"memory")
#define CPWAIT1() asm volatile("cp.async.wait_group 1;":::"memory")
#define LDSM4(r,addr) asm volatile( \
    "ldmatrix.sync.aligned.m8n8.x4.shared.b16 {%0,%1,%2,%3}, [%4];" \
    : "=r"((r)[0]),"=r"((r)[1]),"=r"((r)[2]),"=r"((r)[3]) : "r"(addr))
#define MMA(d,a,b0,b1) asm volatile( \
    "mma.sync.aligned.m16n8k16.row.col.f32.f16.f16.f32 " \
    "{%0,%1,%2,%3}, {%4,%5,%6,%7}, {%8,%9}, {%0,%1,%2,%3};" \
    : "+f"((d)[0]),"+f"((d)[1]),"+f"((d)[2]),"+f"((d)[3]) \
    : "r"((a)[0]),"r"((a)[1]),"r"((a)[2]),"r"((a)[3]),"r"(b0),"r"(b1))

// ---- prep: 2-limb fp16 splits ----
__global__ void splitw_kernel(const float* __restrict__ w) {
    int idx = blockIdx.x*256 + threadIdx.x;
    if (idx >= 3*512*512) return;
    int c = idx & 511, o = (idx >> 9) & 511, t = idx >> 18;
    float v = w[(size_t)o*1536 + c*3 + t];
    __half a1 = __float2half_rn(v);
    g_W1[idx] = a1;
    g_W2[idx] = __float2half_rn(v - __half2float(a1));
}
__global__ void pad_kernel() {
    int b = blockIdx.x, c = threadIdx.x;
    __half z = __float2half_rn(0.f);
    size_t r0 = ((size_t)b*LPAD)*NC + c, r1 = ((size_t)b*LPAD + (LPAD-1))*NC + c;
    g_fT1[r0]=z; g_fT2[r0]=z;
    g_fT1[r1]=z; g_fT2[r1]=z;
}
__global__ __launch_bounds__(256)
void splitfeat_kernel(const float* __restrict__ feat) {
    __shared__ float tile[64][65];
    int b = blockIdx.z, c0 = blockIdx.y*64, l0 = blockIdx.x*64;
    int tj = threadIdx.x & 63, ti = threadIdx.x >> 6;
    const float* src = feat + ((size_t)b*NC + c0)*NL + l0;
#pragma unroll
    for (int i = ti; i < 64; i += 4) tile[i][tj] = src[(size_t)i*NL + tj];
    __syncthreads();
#pragma unroll
    for (int lj = ti; lj < 64; lj += 4) {
        float v = tile[tj][lj];
        __half a1 = __float2half_rn(v);
        size_t dst = ((size_t)b*LPAD + (l0 + lj + 1))*NC + c0 + tj;
        g_fT1[dst] = a1;
        g_fT2[dst] = __float2half_rn(v - __half2float(a1));
    }
}

// ---- conv: CTA 128(o)x128(l); 16 c-chunks of k=32, taps share F window ----
#define ROWB2   80u
#define WTILE2  10240u              // 128 rows * 80B
#define F_OFF2  61440u              // after 6 W tiles
#define FTILE2  10560u              // 132 rows * 80B
#define STG2    82560u
#define CONV_SMEM (2u*STG2)         // 165120 B

__device__ __forceinline__ void load_stage(uint32_t sb, int s,
                                           int b, int l0, int o0, int tid) {
    const uint32_t buf = sb + (uint32_t)(s & 1)*STG2;
    const int c0 = s << 5;
    // W: 6 tiles x 128 rows x 4 quarters = 3072 tasks
#pragma unroll
    for (int i = 0; i < 12; i++) {
        int id = tid + 256*i;
        int r = id & 127, q = (id >> 7) & 3, tl = id >> 9;
        const __half* gw = (tl & 1) ? g_W2 : g_W1;
        size_t src = ((size_t)((tl>>1)*512 + o0 + r))*512 + c0 + q*8;
        CP16(buf + (uint32_t)tl*WTILE2 + (uint32_t)r*ROWB2 + q*16, gw + src);
    }
    // F: 2 limbs x 130 rows x 4 quarters = 1040 tasks
#pragma unroll
    for (int i = 0; i < 5; i++) {
        int id = tid + 256*i;
        if (id < 1040) {
            int q = id & 3, rem = id >> 2;
            int L = rem >= 130 ? 1 : 0;
            int fr = rem - L*130;
            const __half* gf = L ? g_fT2 : g_fT1;
            size_t src = ((size_t)b*LPAD + (size_t)(l0 + fr))*512 + c0 + q*8;
            CP16(buf + F_OFF2 + (uint32_t)L*FTILE2 + (uint32_t)fr*ROWB2 + q*16, gf + src);
        }
    }
}

__global__ __launch_bounds__(256, 1)
void conv_mma_kernel(const float* __restrict__ bias) {
    extern __shared__ char smem[];
    uint32_t sb = smem_u32(smem);
    const int tid = threadIdx.x, lane = tid & 31, w = tid >> 5;
    const int wo = w & 1, wl = w >> 1;
    const int b = blockIdx.z, o0 = blockIdx.y*128, l0 = blockIdx.x*128;

    float acc[4][4][4];
#pragma unroll
    for (int i=0;i<4;i++)
#pragma unroll
        for (int j=0;j<4;j++)
#pragma unroll
            for (int k=0;k<4;k++) acc[i][j][k]=0.f;

    load_stage(sb, 0, b, l0, o0, tid); CPCOMMIT();
    load_stage(sb, 1, b, l0, o0, tid); CPCOMMIT();

    const int lr = lane & 15, lc16 = (lane >> 4) * 16;

    for (int s = 0; s < 16; s++) {
        CPWAIT1();
        __syncthreads();
        const uint32_t buf = sb + (uint32_t)(s & 1)*STG2;
#pragma unroll
        for (int t = 0; t < 3; t++) {
#pragma unroll
            for (int kk = 0; kk < 2; kk++) {
                const uint32_t ko = (uint32_t)(kk*32) + lc16;
                uint32_t a1[4][4], a2[4][4], b1[2][4], b2[2][4];
#pragma unroll
                for (int mt = 0; mt < 4; mt++) {
                    uint32_t r = (uint32_t)(wo*64 + mt*16 + lr)*ROWB2 + ko;
                    LDSM4(a1[mt], buf + (uint32_t)(t*2)*WTILE2 + r);
                    LDSM4(a2[mt], buf + (uint32_t)(t*2+1)*WTILE2 + r);
                }
#pragma unroll
                for (int nt = 0; nt < 2; nt++) {
                    uint32_t r = (uint32_t)(wl*32 + nt*16 + lr + t)*ROWB2 + ko;
                    LDSM4(b1[nt], buf + F_OFF2 + r);
                    LDSM4(b2[nt], buf + F_OFF2 + FTILE2 + r);
                }
#define COMBO(A,B) \
                _Pragma("unroll") \
                for (int mt = 0; mt < 4; mt++) \
                _Pragma("unroll") \
                for (int nt = 0; nt < 2; nt++) { \
                    MMA(acc[mt][2*nt],   A[mt], B[nt][0], B[nt][2]); \
                    MMA(acc[mt][2*nt+1], A[mt], B[nt][1], B[nt][3]); \
                }
                COMBO(a1,b1) COMBO(a1,b2) COMBO(a2,b1)
#undef COMBO
            }
        }
        __syncthreads();
        if (s + 2 < 16) { load_stage(sb, s+2, b, l0, o0, tid); }
        CPCOMMIT();
    }

    // epilogue: stage through smem for coalesced stores
    __syncthreads();
    float* hs = (float*)smem;                      // [128][132]
    const int r0 = lane >> 2, cp = (lane & 3)*2;
#pragma unroll
    for (int mt = 0; mt < 4; mt++) {
        int orow0 = wo*64 + mt*16 + r0;
        float bv0 = __ldg(bias + o0 + orow0), bv1 = __ldg(bias + o0 + orow0 + 8);
#pragma unroll
        for (int nb = 0; nb < 4; nb++) {
            int lc = wl*32 + nb*8 + cp;
            hs[orow0*132 + lc]       = fmaxf(acc[mt][nb][0]+bv0, 0.f);
            hs[orow0*132 + lc + 1]   = fmaxf(acc[mt][nb][1]+bv0, 0.f);
            hs[(orow0+8)*132 + lc]   = fmaxf(acc[mt][nb][2]+bv1, 0.f);
            hs[(orow0+8)*132 + lc+1] = fmaxf(acc[mt][nb][3]+bv1, 0.f);
        }
    }
    __syncthreads();
    float* hb = g_h + (size_t)b*NC*NL;
#pragma unroll
    for (int it = 0; it < 16; it++) {
        int task = tid + 256*it;                   // 4096 tasks
        int o = task >> 5, j = task & 31;
        float4 v = *(float4*)(hs + o*132 + j*4);
        *(float4*)(hb + (size_t)(o0+o)*NL + l0 + j*4) = v;
    }
}

// ---- heads + decode + scores ----
__global__ __launch_bounds__(256)
void proj_kernel(const float* __restrict__ obj_w, const float* __restrict__ obj_b,
                 const float* __restrict__ reg_w, const float* __restrict__ reg_b,
                 float* __restrict__ out) {
    __shared__ float ws[21*512];
    const int b = blockIdx.y, l0 = blockIdx.x*512, tid = threadIdx.x;
    for (int i = tid; i < 7*512;  i += 256) ws[i] = obj_w[i];
    for (int i = tid; i < 14*512; i += 256) ws[3584 + i] = reg_w[i];
    __syncthreads();
    float acc[21][2];
#pragma unroll
    for (int a = 0; a < 21; a++) { acc[a][0]=0.f; acc[a][1]=0.f; }
    const float* hb = g_h + (size_t)b*NC*NL + l0 + tid;
#pragma unroll 4
    for (int c = 0; c < NC; c++) {
        float h0 = hb[(size_t)c*NL], h1 = hb[(size_t)c*NL + 256];
#pragma unroll
        for (int a = 0; a < 21; a++) {
            float wv = ws[a*512 + c];
            acc[a][0] += wv*h0; acc[a][1] += wv*h1;
        }
    }
#pragma unroll
    for (int r = 0; r < 2; r++) {
        int l = l0 + 256*r + tid;
#pragma unroll
        for (int a = 0; a < NA; a++) {
            float ol = acc[a][r] + __ldg(obj_b + a);
            size_t n = (size_t)b*NPA + (size_t)l*NA + a;
            out[OFF_OBJ + n] = ol;
            g_scores[n] = 1.f/(1.f + expf(-ol));
            float tc = acc[7+2*a][r] + __ldg(reg_b + 2*a);
            float tw = acc[7+2*a+1][r] + __ldg(reg_b + 2*a+1);
            out[OFF_REG + 2*n] = tc; out[OFF_REG + 2*n+1] = tw;
            float len = c_lens[a];
            float twc = fminf(fmaxf(tw, -10.f), 10.f);
            float cc = ((float)l + 0.5f) + tc*len;
            float ww = len * expf(twc);
            float s = fminf(fmaxf(cc - 0.5f*ww, 0.f), 8192.f);
            float e = fminf(fmaxf(cc + 0.5f*ww, 0.f), 8192.f);
            e = fminf(fmaxf(e, s + 1e-3f), 8192.f);
            s = fmaxf(fminf(s, e - 1e-3f), 0.f);
            g_boxes[2*n] = s; g_boxes[2*n+1] = e;
        }
    }
}

__global__ void anchors_kernel(float* __restrict__ out) {
    int n = blockIdx.x*blockDim.x + threadIdx.x;
    if (n < NPA) {
        int l = n / NA, a = n % NA;
        float cen = (float)l + 0.5f, half = 0.5f*c_lens[a];
        out[OFF_ANCH + 2*n] = cen - half;
        out[OFF_ANCH + 2*n + 1] = cen + half;
    }
}

// ---- topk + NMS ----
#define TK_SMEM 65536
__global__ __launch_bounds__(512)
void topk_nms_kernel(float* __restrict__ out) {
    extern __shared__ char dynsm[];
    int* hist = (int*)dynsm;
    unsigned long long* keys = (unsigned long long*)dynsm;
    unsigned* smask = (unsigned*)(dynsm + 8192);
    int* eqbuf = (int*)(dynsm + 57344);
    __shared__ float sbox[PRE_K*2];
    __shared__ float ssc[PRE_K];
    __shared__ int skept[POST_K];
    __shared__ int csum[512];
    __shared__ int s_cnt, s_g, s_e, s_nk, s_B, s_ncand;

    const int b = blockIdx.x, tid = threadIdx.x;
    const float* sc = g_scores + (size_t)b*NPA;

    for (int i = tid; i < 16384; i += 512) hist[i] = 0;
    __syncthreads();
    for (int p = tid; p < NPA; p += 512)
        atomicAdd(&hist[__float_as_uint(sc[p]) >> 16], 1);
    __syncthreads();
    int cs = 0;
#pragma unroll 8
    for (int j = 0; j < 32; j++) cs += hist[tid*32 + j];
    csum[tid] = cs;
    __syncthreads();
    if (tid == 0) {
        int acc = 0, tc = 511;
        for (; tc > 0; tc--) { if (acc + csum[tc] >= PRE_K) break; acc += csum[tc]; }
        int B = tc*32;
        for (int j = tc*32 + 31; j >= tc*32; j--) {
            if (acc + hist[j] >= PRE_K) { B = j; break; }
            acc += hist[j];
        }
        s_B = B; s_ncand = acc + hist[B];
    }
    __syncthreads();
    const int B = s_B;
    const int ncand = s_ncand;

    if (ncand <= 1024) {
        if (tid == 0) s_g = 0;
        __syncthreads();
        for (int p = tid; p < NPA; p += 512) {
            unsigned bits = __float_as_uint(sc[p]);
            if ((int)(bits >> 16) >= B) {
                int q = atomicAdd(&s_g, 1);
                keys[q] = ((unsigned long long)bits << 32) |
                          (unsigned long long)(0xFFFFFFFFu - (unsigned)p);
            }
        }
        __syncthreads();
        for (int i = tid + ncand; i < 1024; i += 512) keys[i] = 0ULL;
    } else {
        unsigned lo = (unsigned)B << 16, hi = ((unsigned)B << 16) + 0x10000u;
        for (int it = 0; it < 17 && (hi - lo) > 1u; ++it) {
            unsigned mid = lo + ((hi - lo) >> 1);
            if (tid == 0) s_cnt = 0;
            __syncthreads();
            int c = 0;
            for (int p = tid; p < NPA; p += 512)
                c += (__float_as_uint(sc[p]) >= mid) ? 1 : 0;
#pragma unroll
            for (int o = 16; o; o >>= 1) c += __shfl_down_sync(0xffffffffu, c, o);
            if ((tid & 31) == 0) atomicAdd(&s_cnt, c);
            __syncthreads();
            if (s_cnt >= PRE_K) lo = mid; else hi = mid;
            __syncthreads();
        }
        unsigned V = lo;
        if (tid == 0) { s_g = 0; s_e = 0; }
        __syncthreads();
        for (int p = tid; p < NPA; p += 512) {
            unsigned bits = __float_as_uint(sc[p]);
            if (bits > V) {
                int q = atomicAdd(&s_g, 1);
                if (q < 1024)
                    keys[q] = ((unsigned long long)bits << 32) |
                              (unsigned long long)(0xFFFFFFFFu - (unsigned)p);
            } else if (bits == V) {
                int q = atomicAdd(&s_e, 1);
                if (q < 1024) eqbuf[q] = p;
            }
        }
        __syncthreads();
        int ng = s_g < 1024 ? s_g : 1024;
        int ne = s_e < 1024 ? s_e : 1024;
        for (int i = tid; i < 1024; i += 512) {
            if (i >= ng) {
                int e = i - ng;
                keys[i] = (e < ne)
                    ? (((unsigned long long)V << 32) |
                       (unsigned long long)(0xFFFFFFFFu - (unsigned)eqbuf[e]))
                    : 0ULL;
            }
        }
    }

    for (int k = 2; k <= 1024; k <<= 1)
        for (int j = k >> 1; j > 0; j >>= 1) {
            __syncthreads();
            for (int i = tid; i < 1024; i += 512) {
                int l = i ^ j;
                if (l > i) {
                    unsigned long long a = keys[i], bb = keys[l];
                    bool up = ((i & k) == 0);
                    if (up ? (a < bb) : (a > bb)) { keys[i] = bb; keys[l] = a; }
                }
            }
        }
    __syncthreads();

    for (int i = tid; i < PRE_K; i += 512) {
        unsigned long long kv = keys[i];
        unsigned bits = (unsigned)(kv >> 32);
        if (bits == 0u) { ssc[i] = 0.f; sbox[2*i] = 0.f; sbox[2*i+1] = 0.f; }
        else {
            unsigned ridx = 0xFFFFFFFFu - (unsigned)(kv & 0xFFFFFFFFull);
            ssc[i] = __uint_as_float(bits);
            const float* bp = g_boxes + ((size_t)b*NPA + ridx)*2;
            sbox[2*i] = bp[0]; sbox[2*i+1] = bp[1];
        }
    }
    __syncthreads();

    for (int i = tid; i < PRE_K; i += 512) {
        float si = sbox[2*i], ei = sbox[2*i+1], wi = ei - si;
        for (int w = 0; w < NMW; w++) {
            unsigned m = 0;
            int jb = w*32, jm = i - jb; if (jm > 32) jm = 32;
            for (int jj = 0; jj < jm; jj++) {
                int j = jb + jj;
                float sj = sbox[2*j], ej = sbox[2*j+1];
                float inter = fmaxf(fminf(ei, ej) - fmaxf(si, sj), 0.f);
                float iou = inter / fmaxf(wi + (ej - sj) - inter, 1e-6f);
                if (iou > 0.5f) m |= (1u << jj);
            }
            smask[i*NMW + w] = m;
        }
    }
    __syncthreads();

    if (tid < 32) {
        int lane = tid;
        unsigned keepw = 0;
        int nk = 0;
        for (int i = 0; i < PRE_K; i++) {
            unsigned mw = (lane < NMW) ? smask[i*NMW + lane] : 0u;
            bool sup = __any_sync(0xffffffffu, (mw & keepw) != 0u);
            bool val = (ssc[i] >= 0.1f);
            if (val && !sup) {
                if (lane == (i >> 5)) keepw |= (1u << (i & 31));
                if (lane == 0 && nk < POST_K) skept[nk] = i;
                nk++;
            }
        }
        if (lane == 0) s_nk = (nk < POST_K) ? nk : POST_K;
    }
    __syncthreads();

    int nk = s_nk;
    for (int r = tid; r < POST_K; r += 512) {
        bool on = r < nk;
        int i = on ? skept[r] : 0;
        size_t base = (size_t)b*POST_K + r;
        out[OFF_PROPS + 2*base]   = on ? sbox[2*i]   : 0.f;
        out[OFF_PROPS + 2*base+1] = on ? sbox[2*i+1] : 0.f;
        out[OFF_PSC + base]   = on ? ssc[i] : 0.f;
        out[OFF_PMASK + base] = on ? 1.0f : 0.0f;
    }
}

// ---------------------------------------------------------------------------
extern "C" void kernel_launch(void* const* d_in, const int* in_sizes, int n_in,
                              void* d_out, int out_size) {
    const float* feat   = (const float*)d_in[0];
    const float* conv_w = (const float*)d_in[1];
    const float* conv_b = (const float*)d_in[2];
    const float* obj_w  = (const float*)d_in[3];
    const float* obj_b  = (const float*)d_in[4];
    const float* reg_w  = (const float*)d_in[5];
    const float* reg_b  = (const float*)d_in[6];
    float* out = (float*)d_out;

    cudaFuncSetAttribute(conv_mma_kernel, cudaFuncAttributeMaxDynamicSharedMemorySize, CONV_SMEM);
    cudaFuncSetAttribute(topk_nms_kernel, cudaFuncAttributeMaxDynamicSharedMemorySize, TK_SMEM);

    splitw_kernel<<<(3*512*512 + 255)/256, 256>>>(conv_w);
    pad_kernel<<<NB, 512>>>();
    dim3 sgrid(NL/64, NC/64, NB);
    splitfeat_kernel<<<sgrid, 256>>>(feat);

    dim3 cgrid(NL/128, NC/128, NB);          // (64, 4, 8)
    conv_mma_kernel<<<cgrid, 256, CONV_SMEM>>>(conv_b);

    dim3 pgrid(NL/512, NB);
    proj_kernel<<<pgrid, 256>>>(obj_w, obj_b, reg_w, reg_b, out);

    anchors_kernel<<<(NPA + 255)/256, 256>>>(out);

    topk_nms_kernel<<<NB, 512, TK_SMEM>>>(out);
}

// round 10
// speedup vs baseline: 1.1151x; 1.0157x over previous
#include <cuda_runtime.h>
#include <cuda_fp16.h>
#include <math.h>
#include <stdint.h>

#define NB 8
#define NC 512
#define NL 8192
#define NA 7
#define NPA (NL*NA)
#define PRE_K 600
#define POST_K 100
#define NMW 19
#define LPAD 8194

#define OFF_OBJ  0
#define SZ_OBJ   (NB*NPA)
#define OFF_REG  (SZ_OBJ)
#define SZ_REG   (NB*NPA*2)
#define OFF_ANCH (OFF_REG + SZ_REG)
#define SZ_ANCH  (NPA*2)
#define OFF_PROPS (OFF_ANCH + SZ_ANCH)
#define SZ_PROPS (NB*POST_K*2)
#define OFF_PSC  (OFF_PROPS + SZ_PROPS)
#define OFF_PMASK (OFF_PSC + NB*POST_K)

__device__ float g_pp[(size_t)NB*4*21*NL];      // partial projections, 22MB
__device__ float g_boxes[(size_t)NB*NPA*2];
__device__ float g_scores[(size_t)NB*NPA];
__device__ __align__(256) __half g_fT1[(size_t)NB*LPAD*NC];
__device__ __align__(256) __half g_fT2[(size_t)NB*LPAD*NC];
__device__ __align__(256) __half g_W1[3*512*512];
__device__ __align__(256) __half g_W2[3*512*512];

__constant__ float c_lens[NA] = {1.f,2.f,3.f,4.f,5.f,7.f,9.f};

__device__ __forceinline__ uint32_t smem_u32(const void* p) {
    uint32_t a;
    asm("{ .reg .u64 t; cvta.to.shared.u64 t, %1; cvt.u32.u64 %0, t; }" : "=r"(a) : "l"(p));
    return a;
}
#define CP16(dst,src) asm volatile("cp.async.cg.shared.global [%0], [%1], 16;"::"r"(dst),"l"(src))
#define CPCOMMIT() asm volatile("cp.async.commit_group;":::"memory")
#define CPWAIT1() asm volatile("cp.async.wait_group 1;":::"memory")
#define LDSM4(r,addr) asm volatile( \
    "ldmatrix.sync.aligned.m8n8.x4.shared.b16 {%0,%1,%2,%3}, [%4];" \
    : "=r"((r)[0]),"=r"((r)[1]),"=r"((r)[2]),"=r"((r)[3]) : "r"(addr))
#define MMA(d,a,b0,b1) asm volatile( \
    "mma.sync.aligned.m16n8k16.row.col.f32.f16.f16.f32 " \
    "{%0,%1,%2,%3}, {%4,%5,%6,%7}, {%8,%9}, {%0,%1,%2,%3};" \
    : "+f"((d)[0]),"+f"((d)[1]),"+f"((d)[2]),"+f"((d)[3]) \
    : "r"((a)[0]),"r"((a)[1]),"r"((a)[2]),"r"((a)[3]),"r"(b0),"r"(b1))

// ---- prep: 2-limb fp16 splits ----
__global__ void splitw_kernel(const float* __restrict__ w) {
    int idx = blockIdx.x*256 + threadIdx.x;
    if (idx >= 3*512*512) return;
    int c = idx & 511, o = (idx >> 9) & 511, t = idx >> 18;
    float v = w[(size_t)o*1536 + c*3 + t];
    __half a1 = __float2half_rn(v);
    g_W1[idx] = a1;
    g_W2[idx] = __float2half_rn(v - __half2float(a1));
}
__global__ void pad_kernel() {
    int b = blockIdx.x, c = threadIdx.x;
    __half z = __float2half_rn(0.f);
    size_t r0 = ((size_t)b*LPAD)*NC + c, r1 = ((size_t)b*LPAD + (LPAD-1))*NC + c;
    g_fT1[r0]=z; g_fT2[r0]=z;
    g_fT1[r1]=z; g_fT2[r1]=z;
}
__global__ __launch_bounds__(256)
void splitfeat_kernel(const float* __restrict__ feat) {
    __shared__ float tile[64][65];
    int b = blockIdx.z, c0 = blockIdx.y*64, l0 = blockIdx.x*64;
    int tj = threadIdx.x & 63, ti = threadIdx.x >> 6;
    const float* src = feat + ((size_t)b*NC + c0)*NL + l0;
#pragma unroll
    for (int i = ti; i < 64; i += 4) tile[i][tj] = src[(size_t)i*NL + tj];
    __syncthreads();
#pragma unroll
    for (int lj = ti; lj < 64; lj += 4) {
        float v = tile[tj][lj];
        __half a1 = __float2half_rn(v);
        size_t dst = ((size_t)b*LPAD + (l0 + lj + 1))*NC + c0 + tj;
        g_fT1[dst] = a1;
        g_fT2[dst] = __float2half_rn(v - __half2float(a1));
    }
}

// ---- conv + fused partial projection ----
#define ROWB2   80u
#define WTILE2  10240u
#define F_OFF2  61440u
#define FTILE2  10560u
#define STG2    82560u
#define CONV_SMEM (2u*STG2)         // 165120 B

__device__ __forceinline__ void load_stage(uint32_t sb, int s,
                                           int b, int l0, int o0, int tid) {
    const uint32_t buf = sb + (uint32_t)(s & 1)*STG2;
    const int c0 = s << 5;
#pragma unroll
    for (int i = 0; i < 12; i++) {
        int id = tid + 256*i;
        int r = id & 127, q = (id >> 7) & 3, tl = id >> 9;
        const __half* gw = (tl & 1) ? g_W2 : g_W1;
        size_t src = ((size_t)((tl>>1)*512 + o0 + r))*512 + c0 + q*8;
        CP16(buf + (uint32_t)tl*WTILE2 + (uint32_t)r*ROWB2 + q*16, gw + src);
    }
#pragma unroll
    for (int i = 0; i < 5; i++) {
        int id = tid + 256*i;
        if (id < 1040) {
            int q = id & 3, rem = id >> 2;
            int L = rem >= 130 ? 1 : 0;
            int fr = rem - L*130;
            const __half* gf = L ? g_fT2 : g_fT1;
            size_t src = ((size_t)b*LPAD + (size_t)(l0 + fr))*512 + c0 + q*8;
            CP16(buf + F_OFF2 + (uint32_t)L*FTILE2 + (uint32_t)fr*ROWB2 + q*16, gf + src);
        }
    }
}

__global__ __launch_bounds__(256, 1)
void conv_mma_kernel(const float* __restrict__ bias,
                     const float* __restrict__ obj_w,
                     const float* __restrict__ reg_w) {
    extern __shared__ char smem[];
    uint32_t sb = smem_u32(smem);
    const int tid = threadIdx.x, lane = tid & 31, w = tid >> 5;
    const int wo = w & 1, wl = w >> 1;
    const int b = blockIdx.z, ob = blockIdx.y, o0 = ob*128, l0 = blockIdx.x*128;

    float acc[4][4][4];
#pragma unroll
    for (int i=0;i<4;i++)
#pragma unroll
        for (int j=0;j<4;j++)
#pragma unroll
            for (int k=0;k<4;k++) acc[i][j][k]=0.f;

    load_stage(sb, 0, b, l0, o0, tid); CPCOMMIT();
    load_stage(sb, 1, b, l0, o0, tid); CPCOMMIT();

    const int lr = lane & 15, lc16 = (lane >> 4) * 16;

    for (int s = 0; s < 16; s++) {
        CPWAIT1();
        __syncthreads();
        const uint32_t buf = sb + (uint32_t)(s & 1)*STG2;
#pragma unroll
        for (int t = 0; t < 3; t++) {
#pragma unroll
            for (int kk = 0; kk < 2; kk++) {
                const uint32_t ko = (uint32_t)(kk*32) + lc16;
                uint32_t a1[4][4], a2[4][4], b1[2][4], b2[2][4];
#pragma unroll
                for (int mt = 0; mt < 4; mt++) {
                    uint32_t r = (uint32_t)(wo*64 + mt*16 + lr)*ROWB2 + ko;
                    LDSM4(a1[mt], buf + (uint32_t)(t*2)*WTILE2 + r);
                    LDSM4(a2[mt], buf + (uint32_t)(t*2+1)*WTILE2 + r);
                }
#pragma unroll
                for (int nt = 0; nt < 2; nt++) {
                    uint32_t r = (uint32_t)(wl*32 + nt*16 + lr + t)*ROWB2 + ko;
                    LDSM4(b1[nt], buf + F_OFF2 + r);
                    LDSM4(b2[nt], buf + F_OFF2 + FTILE2 + r);
                }
#define COMBO(A,B) \
                _Pragma("unroll") \
                for (int mt = 0; mt < 4; mt++) \
                _Pragma("unroll") \
                for (int nt = 0; nt < 2; nt++) { \
                    MMA(acc[mt][2*nt],   A[mt], B[nt][0], B[nt][2]); \
                    MMA(acc[mt][2*nt+1], A[mt], B[nt][1], B[nt][3]); \
                }
                COMBO(a1,b1) COMBO(a1,b2) COMBO(a2,b1)
#undef COMBO
            }
        }
        __syncthreads();
        if (s + 2 < 16) { load_stage(sb, s+2, b, l0, o0, tid); }
        CPCOMMIT();
    }

    // ---- fused epilogue: h tile -> smem, then partial 21-ch projection ----
    __syncthreads();
    float* hs = (float*)smem;                      // [128][132] floats
    float* w21 = hs + 128*132;                     // [21][128]
    const int r0 = lane >> 2, cp = (lane & 3)*2;
#pragma unroll
    for (int mt = 0; mt < 4; mt++) {
        int orow0 = wo*64 + mt*16 + r0;
        float bv0 = __ldg(bias + o0 + orow0), bv1 = __ldg(bias + o0 + orow0 + 8);
#pragma unroll
        for (int nb = 0; nb < 4; nb++) {
            int lc = wl*32 + nb*8 + cp;
            hs[orow0*132 + lc]       = fmaxf(acc[mt][nb][0]+bv0, 0.f);
            hs[orow0*132 + lc + 1]   = fmaxf(acc[mt][nb][1]+bv0, 0.f);
            hs[(orow0+8)*132 + lc]   = fmaxf(acc[mt][nb][2]+bv1, 0.f);
            hs[(orow0+8)*132 + lc+1] = fmaxf(acc[mt][nb][3]+bv1, 0.f);
        }
    }
    for (int i = tid; i < 21*128; i += 256) {
        int a = i >> 7, o = i & 127;
        w21[i] = (a < 7) ? __ldg(obj_w + a*512 + o0 + o)
                         : __ldg(reg_w + (a-7)*512 + o0 + o);
    }
    __syncthreads();

    float* pp = g_pp + (((size_t)b*4 + ob)*21)*NL + l0;
    for (int i = tid; i < 21*128; i += 256) {
        int a = i >> 7, l = i & 127;
        float s0 = 0.f;
        const float* wr = w21 + a*128;
#pragma unroll 8
        for (int o = 0; o < 128; o++) s0 += wr[o] * hs[o*132 + l];
        pp[(size_t)a*NL + l] = s0;
    }
}

// ---- decode: sum 4 partials + bias + sigmoid + box decode ----
__global__ __launch_bounds__(256)
void decode_kernel(const float* __restrict__ obj_b,
                   const float* __restrict__ reg_b,
                   float* __restrict__ out) {
    const int b = blockIdx.y;
    const int l = blockIdx.x*256 + threadIdx.x;
    const float* pb = g_pp + ((size_t)b*4*21)*NL + l;

    float sv[21];
#pragma unroll
    for (int a = 0; a < 21; a++) {
        float s0 = pb[(size_t)a*NL];
        s0 += pb[(size_t)(21 + a)*NL];
        s0 += pb[(size_t)(42 + a)*NL];
        s0 += pb[(size_t)(63 + a)*NL];
        sv[a] = s0;
    }
#pragma unroll
    for (int a = 0; a < NA; a++) {
        float ol = sv[a] + __ldg(obj_b + a);
        size_t n = (size_t)b*NPA + (size_t)l*NA + a;
        out[OFF_OBJ + n] = ol;
        g_scores[n] = 1.f/(1.f + expf(-ol));
        float tc = sv[7+2*a]   + __ldg(reg_b + 2*a);
        float tw = sv[7+2*a+1] + __ldg(reg_b + 2*a+1);
        out[OFF_REG + 2*n] = tc; out[OFF_REG + 2*n+1] = tw;
        float len = c_lens[a];
        float twc = fminf(fmaxf(tw, -10.f), 10.f);
        float cc = ((float)l + 0.5f) + tc*len;
        float ww = len * expf(twc);
        float s = fminf(fmaxf(cc - 0.5f*ww, 0.f), 8192.f);
        float e = fminf(fmaxf(cc + 0.5f*ww, 0.f), 8192.f);
        e = fminf(fmaxf(e, s + 1e-3f), 8192.f);
        s = fmaxf(fminf(s, e - 1e-3f), 0.f);
        g_boxes[2*n] = s; g_boxes[2*n+1] = e;
    }
}

__global__ void anchors_kernel(float* __restrict__ out) {
    int n = blockIdx.x*blockDim.x + threadIdx.x;
    if (n < NPA) {
        int l = n / NA, a = n % NA;
        float cen = (float)l + 0.5f, half = 0.5f*c_lens[a];
        out[OFF_ANCH + 2*n] = cen - half;
        out[OFF_ANCH + 2*n + 1] = cen + half;
    }
}

// ---- topk + NMS ----
#define TK_SMEM 65536
__global__ __launch_bounds__(512)
void topk_nms_kernel(float* __restrict__ out) {
    extern __shared__ char dynsm[];
    int* hist = (int*)dynsm;
    unsigned long long* keys = (unsigned long long*)dynsm;
    unsigned* smask = (unsigned*)(dynsm + 8192);
    int* eqbuf = (int*)(dynsm + 57344);
    __shared__ float sbox[PRE_K*2];
    __shared__ float ssc[PRE_K];
    __shared__ int skept[POST_K];
    __shared__ int csum[512];
    __shared__ int s_cnt, s_g, s_e, s_nk, s_B, s_ncand;

    const int b = blockIdx.x, tid = threadIdx.x;
    const float* sc = g_scores + (size_t)b*NPA;

    for (int i = tid; i < 16384; i += 512) hist[i] = 0;
    __syncthreads();
    for (int p = tid; p < NPA; p += 512)
        atomicAdd(&hist[__float_as_uint(sc[p]) >> 16], 1);
    __syncthreads();
    int cs = 0;
#pragma unroll 8
    for (int j = 0; j < 32; j++) cs += hist[tid*32 + j];
    csum[tid] = cs;
    __syncthreads();
    if (tid == 0) {
        int acc = 0, tc = 511;
        for (; tc > 0; tc--) { if (acc + csum[tc] >= PRE_K) break; acc += csum[tc]; }
        int B = tc*32;
        for (int j = tc*32 + 31; j >= tc*32; j--) {
            if (acc + hist[j] >= PRE_K) { B = j; break; }
            acc += hist[j];
        }
        s_B = B; s_ncand = acc + hist[B];
    }
    __syncthreads();
    const int B = s_B;
    const int ncand = s_ncand;

    if (ncand <= 1024) {
        if (tid == 0) s_g = 0;
        __syncthreads();
        for (int p = tid; p < NPA; p += 512) {
            unsigned bits = __float_as_uint(sc[p]);
            if ((int)(bits >> 16) >= B) {
                int q = atomicAdd(&s_g, 1);
                keys[q] = ((unsigned long long)bits << 32) |
                          (unsigned long long)(0xFFFFFFFFu - (unsigned)p);
            }
        }
        __syncthreads();
        for (int i = tid + ncand; i < 1024; i += 512) keys[i] = 0ULL;
    } else {
        unsigned lo = (unsigned)B << 16, hi = ((unsigned)B << 16) + 0x10000u;
        for (int it = 0; it < 17 && (hi - lo) > 1u; ++it) {
            unsigned mid = lo + ((hi - lo) >> 1);
            if (tid == 0) s_cnt = 0;
            __syncthreads();
            int c = 0;
            for (int p = tid; p < NPA; p += 512)
                c += (__float_as_uint(sc[p]) >= mid) ? 1 : 0;
#pragma unroll
            for (int o = 16; o; o >>= 1) c += __shfl_down_sync(0xffffffffu, c, o);
            if ((tid & 31) == 0) atomicAdd(&s_cnt, c);
            __syncthreads();
            if (s_cnt >= PRE_K) lo = mid; else hi = mid;
            __syncthreads();
        }
        unsigned V = lo;
        if (tid == 0) { s_g = 0; s_e = 0; }
        __syncthreads();
        for (int p = tid; p < NPA; p += 512) {
            unsigned bits = __float_as_uint(sc[p]);
            if (bits > V) {
                int q = atomicAdd(&s_g, 1);
                if (q < 1024)
                    keys[q] = ((unsigned long long)bits << 32) |
                              (unsigned long long)(0xFFFFFFFFu - (unsigned)p);
            } else if (bits == V) {
                int q = atomicAdd(&s_e, 1);
                if (q < 1024) eqbuf[q] = p;
            }
        }
        __syncthreads();
        int ng = s_g < 1024 ? s_g : 1024;
        int ne = s_e < 1024 ? s_e : 1024;
        for (int i = tid; i < 1024; i += 512) {
            if (i >= ng) {
                int e = i - ng;
                keys[i] = (e < ne)
                    ? (((unsigned long long)V << 32) |
                       (unsigned long long)(0xFFFFFFFFu - (unsigned)eqbuf[e]))
                    : 0ULL;
            }
        }
    }

    for (int k = 2; k <= 1024; k <<= 1)
        for (int j = k >> 1; j > 0; j >>= 1) {
            __syncthreads();
            for (int i = tid; i < 1024; i += 512) {
                int l = i ^ j;
                if (l > i) {
                    unsigned long long a = keys[i], bb = keys[l];
                    bool up = ((i & k) == 0);
                    if (up ? (a < bb) : (a > bb)) { keys[i] = bb; keys[l] = a; }
                }
            }
        }
    __syncthreads();

    for (int i = tid; i < PRE_K; i += 512) {
        unsigned long long kv = keys[i];
        unsigned bits = (unsigned)(kv >> 32);
        if (bits == 0u) { ssc[i] = 0.f; sbox[2*i] = 0.f; sbox[2*i+1] = 0.f; }
        else {
            unsigned ridx = 0xFFFFFFFFu - (unsigned)(kv & 0xFFFFFFFFull);
            ssc[i] = __uint_as_float(bits);
            const float* bp = g_boxes + ((size_t)b*NPA + ridx)*2;
            sbox[2*i] = bp[0]; sbox[2*i+1] = bp[1];
        }
    }
    __syncthreads();

    for (int i = tid; i < PRE_K; i += 512) {
        float si = sbox[2*i], ei = sbox[2*i+1], wi = ei - si;
        for (int w = 0; w < NMW; w++) {
            unsigned m = 0;
            int jb = w*32, jm = i - jb; if (jm > 32) jm = 32;
            for (int jj = 0; jj < jm; jj++) {
                int j = jb + jj;
                float sj = sbox[2*j], ej = sbox[2*j+1];
                float inter = fmaxf(fminf(ei, ej) - fmaxf(si, sj), 0.f);
                float iou = inter / fmaxf(wi + (ej - sj) - inter, 1e-6f);
                if (iou > 0.5f) m |= (1u << jj);
            }
            smask[i*NMW + w] = m;
        }
    }
    __syncthreads();

    if (tid < 32) {
        int lane = tid;
        unsigned keepw = 0;
        int nk = 0;
        for (int i = 0; i < PRE_K; i++) {
            unsigned mw = (lane < NMW) ? smask[i*NMW + lane] : 0u;
            bool sup = __any_sync(0xffffffffu, (mw & keepw) != 0u);
            bool val = (ssc[i] >= 0.1f);
            if (val && !sup) {
                if (lane == (i >> 5)) keepw |= (1u << (i & 31));
                if (lane == 0 && nk < POST_K) skept[nk] = i;
                nk++;
            }
        }
        if (lane == 0) s_nk = (nk < POST_K) ? nk : POST_K;
    }
    __syncthreads();

    int nk = s_nk;
    for (int r = tid; r < POST_K; r += 512) {
        bool on = r < nk;
        int i = on ? skept[r] : 0;
        size_t base = (size_t)b*POST_K + r;
        out[OFF_PROPS + 2*base]   = on ? sbox[2*i]   : 0.f;
        out[OFF_PROPS + 2*base+1] = on ? sbox[2*i+1] : 0.f;
        out[OFF_PSC + base]   = on ? ssc[i] : 0.f;
        out[OFF_PMASK + base] = on ? 1.0f : 0.0f;
    }
}

// ---------------------------------------------------------------------------
extern "C" void kernel_launch(void* const* d_in, const int* in_sizes, int n_in,
                              void* d_out, int out_size) {
    const float* feat   = (const float*)d_in[0];
    const float* conv_w = (const float*)d_in[1];
    const float* conv_b = (const float*)d_in[2];
    const float* obj_w  = (const float*)d_in[3];
    const float* obj_b  = (const float*)d_in[4];
    const float* reg_w  = (const float*)d_in[5];
    const float* reg_b  = (const float*)d_in[6];
    float* out = (float*)d_out;

    cudaFuncSetAttribute(conv_mma_kernel, cudaFuncAttributeMaxDynamicSharedMemorySize, CONV_SMEM);
    cudaFuncSetAttribute(topk_nms_kernel, cudaFuncAttributeMaxDynamicSharedMemorySize, TK_SMEM);

    splitw_kernel<<<(3*512*512 + 255)/256, 256>>>(conv_w);
    pad_kernel<<<NB, 512>>>();
    dim3 sgrid(NL/64, NC/64, NB);
    splitfeat_kernel<<<sgrid, 256>>>(feat);

    dim3 cgrid(NL/128, NC/128, NB);          // (64, 4, 8)
    conv_mma_kernel<<<cgrid, 256, CONV_SMEM>>>(conv_b, obj_w, reg_w);

    dim3 dgrid(NL/256, NB);
    decode_kernel<<<dgrid, 256>>>(obj_b, reg_b, out);

    anchors_kernel<<<(NPA + 255)/256, 256>>>(out);

    topk_nms_kernel<<<NB, 512, TK_SMEM>>>(out);
}

// round 11
// speedup vs baseline: 1.1320x; 1.0151x over previous
#include <cuda_runtime.h>
#include <cuda_fp16.h>
#include <math.h>
#include <stdint.h>

#define NB 8
#define NC 512
#define NL 8192
#define NA 7
#define NPA (NL*NA)
#define PRE_K 600
#define POST_K 100
#define NMW 19
#define LPAD 8194

#define OFF_OBJ  0
#define SZ_OBJ   (NB*NPA)
#define OFF_REG  (SZ_OBJ)
#define SZ_REG   (NB*NPA*2)
#define OFF_ANCH (OFF_REG + SZ_REG)
#define SZ_ANCH  (NPA*2)
#define OFF_PROPS (OFF_ANCH + SZ_ANCH)
#define SZ_PROPS (NB*POST_K*2)
#define OFF_PSC  (OFF_PROPS + SZ_PROPS)
#define OFF_PMASK (OFF_PSC + NB*POST_K)

__device__ float g_pp[(size_t)NB*4*21*NL];      // partial projections, 22MB
__device__ float g_boxes[(size_t)NB*NPA*2];
__device__ float g_scores[(size_t)NB*NPA];
__device__ __align__(256) __half g_fT1[(size_t)NB*LPAD*NC];
__device__ __align__(256) __half g_fT2[(size_t)NB*LPAD*NC];
__device__ __align__(256) __half g_W1[3*512*512];
__device__ __align__(256) __half g_W2[3*512*512];

__constant__ float c_lens[NA] = {1.f,2.f,3.f,4.f,5.f,7.f,9.f};

__device__ __forceinline__ uint32_t smem_u32(const void* p) {
    uint32_t a;
    asm("{ .reg .u64 t; cvta.to.shared.u64 t, %1; cvt.u32.u64 %0, t; }" : "=r"(a) : "l"(p));
    return a;
}
#define CP16(dst,src) asm volatile("cp.async.cg.shared.global [%0], [%1], 16;"::"r"(dst),"l"(src))
#define CPCOMMIT() asm volatile("cp.async.commit_group;":::"memory")
#define CPWAIT1() asm volatile("cp.async.wait_group 1;":::"memory")
#define LDSM4(r,addr) asm volatile( \
    "ldmatrix.sync.aligned.m8n8.x4.shared.b16 {%0,%1,%2,%3}, [%4];" \
    : "=r"((r)[0]),"=r"((r)[1]),"=r"((r)[2]),"=r"((r)[3]) : "r"(addr))
#define MMA(d,a,b0,b1) asm volatile( \
    "mma.sync.aligned.m16n8k16.row.col.f32.f16.f16.f32 " \
    "{%0,%1,%2,%3}, {%4,%5,%6,%7}, {%8,%9}, {%0,%1,%2,%3};" \
    : "+f"((d)[0]),"+f"((d)[1]),"+f"((d)[2]),"+f"((d)[3]) \
    : "r"((a)[0]),"r"((a)[1]),"r"((a)[2]),"r"((a)[3]),"r"(b0),"r"(b1))
#define MMAH(d,a,b0,b1) asm volatile( \
    "mma.sync.aligned.m16n8k16.row.col.f16.f16.f16.f16 " \
    "{%0,%1}, {%2,%3,%4,%5}, {%6,%7}, {%0,%1};" \
    : "+r"((d)[0]),"+r"((d)[1]) \
    : "r"((a)[0]),"r"((a)[1]),"r"((a)[2]),"r"((a)[3]),"r"(b0),"r"(b1))

// ---- prep: 2-limb fp16 splits ----
__global__ void splitw_kernel(const float* __restrict__ w) {
    int idx = blockIdx.x*256 + threadIdx.x;
    if (idx >= 3*512*512) return;
    int c = idx & 511, o = (idx >> 9) & 511, t = idx >> 18;
    float v = w[(size_t)o*1536 + c*3 + t];
    __half a1 = __float2half_rn(v);
    g_W1[idx] = a1;
    g_W2[idx] = __float2half_rn(v - __half2float(a1));
}
__global__ void pad_kernel() {
    int b = blockIdx.x, c = threadIdx.x;
    __half z = __float2half_rn(0.f);
    size_t r0 = ((size_t)b*LPAD)*NC + c, r1 = ((size_t)b*LPAD + (LPAD-1))*NC + c;
    g_fT1[r0]=z; g_fT2[r0]=z;
    g_fT1[r1]=z; g_fT2[r1]=z;
}
__global__ __launch_bounds__(256)
void splitfeat_kernel(const float* __restrict__ feat) {
    __shared__ float tile[64][65];
    int b = blockIdx.z, c0 = blockIdx.y*64, l0 = blockIdx.x*64;
    int tj = threadIdx.x & 63, ti = threadIdx.x >> 6;
    const float* src = feat + ((size_t)b*NC + c0)*NL + l0;
#pragma unroll
    for (int i = ti; i < 64; i += 4) tile[i][tj] = src[(size_t)i*NL + tj];
    __syncthreads();
#pragma unroll
    for (int lj = ti; lj < 64; lj += 4) {
        float v = tile[tj][lj];
        __half a1 = __float2half_rn(v);
        size_t dst = ((size_t)b*LPAD + (l0 + lj + 1))*NC + c0 + tj;
        g_fT1[dst] = a1;
        g_fT2[dst] = __float2half_rn(v - __half2float(a1));
    }
}

// ---- conv + fused partial projection ----
#define ROWB2   80u
#define WTILE2  10240u
#define F_OFF2  61440u
#define FTILE2  10560u
#define STG2    82560u
#define CONV_SMEM (2u*STG2)         // 165120 B

__device__ __forceinline__ void load_stage(uint32_t sb, int s,
                                           int b, int l0, int o0, int tid) {
    const uint32_t buf = sb + (uint32_t)(s & 1)*STG2;
    const int c0 = s << 5;
#pragma unroll
    for (int i = 0; i < 12; i++) {
        int id = tid + 256*i;
        int r = id & 127, q = (id >> 7) & 3, tl = id >> 9;
        const __half* gw = (tl & 1) ? g_W2 : g_W1;
        size_t src = ((size_t)((tl>>1)*512 + o0 + r))*512 + c0 + q*8;
        CP16(buf + (uint32_t)tl*WTILE2 + (uint32_t)r*ROWB2 + q*16, gw + src);
    }
#pragma unroll
    for (int i = 0; i < 5; i++) {
        int id = tid + 256*i;
        if (id < 1040) {
            int q = id & 3, rem = id >> 2;
            int L = rem >= 130 ? 1 : 0;
            int fr = rem - L*130;
            const __half* gf = L ? g_fT2 : g_fT1;
            size_t src = ((size_t)b*LPAD + (size_t)(l0 + fr))*512 + c0 + q*8;
            CP16(buf + F_OFF2 + (uint32_t)L*FTILE2 + (uint32_t)fr*ROWB2 + q*16, gf + src);
        }
    }
}

__global__ __launch_bounds__(256, 1)
void conv_mma_kernel(const float* __restrict__ bias,
                     const float* __restrict__ obj_w,
                     const float* __restrict__ reg_w) {
    extern __shared__ char smem[];
    uint32_t sb = smem_u32(smem);
    const int tid = threadIdx.x, lane = tid & 31, w = tid >> 5;
    const int wo = w & 1, wl = w >> 1;
    const int b = blockIdx.z, ob = blockIdx.y, o0 = ob*128, l0 = blockIdx.x*128;

    float acc[4][4][4];
    uint32_t acc16[4][4][2];
#pragma unroll
    for (int i=0;i<4;i++)
#pragma unroll
        for (int j=0;j<4;j++) {
#pragma unroll
            for (int k=0;k<4;k++) acc[i][j][k]=0.f;
            acc16[i][j][0]=0u; acc16[i][j][1]=0u;
        }

    load_stage(sb, 0, b, l0, o0, tid); CPCOMMIT();
    load_stage(sb, 1, b, l0, o0, tid); CPCOMMIT();

    const int lr = lane & 15, lc16 = (lane >> 4) * 16;

    for (int s = 0; s < 16; s++) {
        CPWAIT1();
        __syncthreads();
        const uint32_t buf = sb + (uint32_t)(s & 1)*STG2;
#pragma unroll
        for (int t = 0; t < 3; t++) {
#pragma unroll
            for (int kk = 0; kk < 2; kk++) {
                const uint32_t ko = (uint32_t)(kk*32) + lc16;
                uint32_t a1[4][4], a2[4][4], b1[2][4], b2[2][4];
#pragma unroll
                for (int mt = 0; mt < 4; mt++) {
                    uint32_t r = (uint32_t)(wo*64 + mt*16 + lr)*ROWB2 + ko;
                    LDSM4(a1[mt], buf + (uint32_t)(t*2)*WTILE2 + r);
                    LDSM4(a2[mt], buf + (uint32_t)(t*2+1)*WTILE2 + r);
                }
#pragma unroll
                for (int nt = 0; nt < 2; nt++) {
                    uint32_t r = (uint32_t)(wl*32 + nt*16 + lr + t)*ROWB2 + ko;
                    LDSM4(b1[nt], buf + F_OFF2 + r);
                    LDSM4(b2[nt], buf + F_OFF2 + FTILE2 + r);
                }
                // main product, f32 accumulators
#pragma unroll
                for (int mt = 0; mt < 4; mt++)
#pragma unroll
                for (int nt = 0; nt < 2; nt++) {
                    MMA(acc[mt][2*nt],   a1[mt], b1[nt][0], b1[nt][2]);
                    MMA(acc[mt][2*nt+1], a1[mt], b1[nt][1], b1[nt][3]);
                }
                // cross products, f16 accumulators
#pragma unroll
                for (int mt = 0; mt < 4; mt++)
#pragma unroll
                for (int nt = 0; nt < 2; nt++) {
                    MMAH(acc16[mt][2*nt],   a1[mt], b2[nt][0], b2[nt][2]);
                    MMAH(acc16[mt][2*nt+1], a1[mt], b2[nt][1], b2[nt][3]);
                    MMAH(acc16[mt][2*nt],   a2[mt], b1[nt][0], b1[nt][2]);
                    MMAH(acc16[mt][2*nt+1], a2[mt], b1[nt][1], b1[nt][3]);
                }
            }
        }
        __syncthreads();
        if (s + 2 < 16) { load_stage(sb, s+2, b, l0, o0, tid); }
        CPCOMMIT();
    }

    // ---- fused epilogue: h tile -> smem, then partial 21-ch projection ----
    __syncthreads();
    float* hs = (float*)smem;                      // [128][132] floats
    float* w21 = hs + 128*132;                     // [21][128]
    const int r0 = lane >> 2, cp = (lane & 3)*2;
#pragma unroll
    for (int mt = 0; mt < 4; mt++) {
        int orow0 = wo*64 + mt*16 + r0;
        float bv0 = __ldg(bias + o0 + orow0), bv1 = __ldg(bias + o0 + orow0 + 8);
#pragma unroll
        for (int nb = 0; nb < 4; nb++) {
            int lc = wl*32 + nb*8 + cp;
            __half2 x0 = *(__half2*)&acc16[mt][nb][0];
            __half2 x1 = *(__half2*)&acc16[mt][nb][1];
            hs[orow0*132 + lc]       = fmaxf(acc[mt][nb][0] + __half2float(x0.x) + bv0, 0.f);
            hs[orow0*132 + lc + 1]   = fmaxf(acc[mt][nb][1] + __half2float(x0.y) + bv0, 0.f);
            hs[(orow0+8)*132 + lc]   = fmaxf(acc[mt][nb][2] + __half2float(x1.x) + bv1, 0.f);
            hs[(orow0+8)*132 + lc+1] = fmaxf(acc[mt][nb][3] + __half2float(x1.y) + bv1, 0.f);
        }
    }
    for (int i = tid; i < 21*128; i += 256) {
        int a = i >> 7, o = i & 127;
        w21[i] = (a < 7) ? __ldg(obj_w + a*512 + o0 + o)
                         : __ldg(reg_w + (a-7)*512 + o0 + o);
    }
    __syncthreads();

    float* pp = g_pp + (((size_t)b*4 + ob)*21)*NL + l0;
    for (int i = tid; i < 21*128; i += 256) {
        int a = i >> 7, l = i & 127;
        float s0 = 0.f;
        const float* wr = w21 + a*128;
#pragma unroll 8
        for (int o = 0; o < 128; o++) s0 += wr[o] * hs[o*132 + l];
        pp[(size_t)a*NL + l] = s0;
    }
}

// ---- decode: sum 4 partials + bias + sigmoid + box decode ----
__global__ __launch_bounds__(256)
void decode_kernel(const float* __restrict__ obj_b,
                   const float* __restrict__ reg_b,
                   float* __restrict__ out) {
    const int b = blockIdx.y;
    const int l = blockIdx.x*256 + threadIdx.x;
    const float* pb = g_pp + ((size_t)b*4*21)*NL + l;

    float sv[21];
#pragma unroll
    for (int a = 0; a < 21; a++) {
        float s0 = pb[(size_t)a*NL];
        s0 += pb[(size_t)(21 + a)*NL];
        s0 += pb[(size_t)(42 + a)*NL];
        s0 += pb[(size_t)(63 + a)*NL];
        sv[a] = s0;
    }
#pragma unroll
    for (int a = 0; a < NA; a++) {
        float ol = sv[a] + __ldg(obj_b + a);
        size_t n = (size_t)b*NPA + (size_t)l*NA + a;
        out[OFF_OBJ + n] = ol;
        g_scores[n] = 1.f/(1.f + expf(-ol));
        float tc = sv[7+2*a]   + __ldg(reg_b + 2*a);
        float tw = sv[7+2*a+1] + __ldg(reg_b + 2*a+1);
        out[OFF_REG + 2*n] = tc; out[OFF_REG + 2*n+1] = tw;
        float len = c_lens[a];
        float twc = fminf(fmaxf(tw, -10.f), 10.f);
        float cc = ((float)l + 0.5f) + tc*len;
        float ww = len * expf(twc);
        float s = fminf(fmaxf(cc - 0.5f*ww, 0.f), 8192.f);
        float e = fminf(fmaxf(cc + 0.5f*ww, 0.f), 8192.f);
        e = fminf(fmaxf(e, s + 1e-3f), 8192.f);
        s = fmaxf(fminf(s, e - 1e-3f), 0.f);
        g_boxes[2*n] = s; g_boxes[2*n+1] = e;
    }
}

__global__ void anchors_kernel(float* __restrict__ out) {
    int n = blockIdx.x*blockDim.x + threadIdx.x;
    if (n < NPA) {
        int l = n / NA, a = n % NA;
        float cen = (float)l + 0.5f, half = 0.5f*c_lens[a];
        out[OFF_ANCH + 2*n] = cen - half;
        out[OFF_ANCH + 2*n + 1] = cen + half;
    }
}

// ---- topk + NMS ----
#define TK_SMEM 65536
__global__ __launch_bounds__(512)
void topk_nms_kernel(float* __restrict__ out) {
    extern __shared__ char dynsm[];
    int* hist = (int*)dynsm;
    unsigned long long* keys = (unsigned long long*)dynsm;
    unsigned* smask = (unsigned*)(dynsm + 8192);
    int* eqbuf = (int*)(dynsm + 57344);
    __shared__ float sbox[PRE_K*2];
    __shared__ float ssc[PRE_K];
    __shared__ int skept[POST_K];
    __shared__ int csum[512];
    __shared__ int s_cnt, s_g, s_e, s_nk, s_B, s_ncand;

    const int b = blockIdx.x, tid = threadIdx.x;
    const float* sc = g_scores + (size_t)b*NPA;

    for (int i = tid; i < 16384; i += 512) hist[i] = 0;
    __syncthreads();
    for (int p = tid; p < NPA; p += 512)
        atomicAdd(&hist[__float_as_uint(sc[p]) >> 16], 1);
    __syncthreads();
    int cs = 0;
#pragma unroll 8
    for (int j = 0; j < 32; j++) cs += hist[tid*32 + j];
    csum[tid] = cs;
    __syncthreads();
    if (tid == 0) {
        int acc = 0, tc = 511;
        for (; tc > 0; tc--) { if (acc + csum[tc] >= PRE_K) break; acc += csum[tc]; }
        int B = tc*32;
        for (int j = tc*32 + 31; j >= tc*32; j--) {
            if (acc + hist[j] >= PRE_K) { B = j; break; }
            acc += hist[j];
        }
        s_B = B; s_ncand = acc + hist[B];
    }
    __syncthreads();
    const int B = s_B;
    const int ncand = s_ncand;

    if (ncand <= 1024) {
        if (tid == 0) s_g = 0;
        __syncthreads();
        for (int p = tid; p < NPA; p += 512) {
            unsigned bits = __float_as_uint(sc[p]);
            if ((int)(bits >> 16) >= B) {
                int q = atomicAdd(&s_g, 1);
                keys[q] = ((unsigned long long)bits << 32) |
                          (unsigned long long)(0xFFFFFFFFu - (unsigned)p);
            }
        }
        __syncthreads();
        for (int i = tid + ncand; i < 1024; i += 512) keys[i] = 0ULL;
    } else {
        unsigned lo = (unsigned)B << 16, hi = ((unsigned)B << 16) + 0x10000u;
        for (int it = 0; it < 17 && (hi - lo) > 1u; ++it) {
            unsigned mid = lo + ((hi - lo) >> 1);
            if (tid == 0) s_cnt = 0;
            __syncthreads();
            int c = 0;
            for (int p = tid; p < NPA; p += 512)
                c += (__float_as_uint(sc[p]) >= mid) ? 1 : 0;
#pragma unroll
            for (int o = 16; o; o >>= 1) c += __shfl_down_sync(0xffffffffu, c, o);
            if ((tid & 31) == 0) atomicAdd(&s_cnt, c);
            __syncthreads();
            if (s_cnt >= PRE_K) lo = mid; else hi = mid;
            __syncthreads();
        }
        unsigned V = lo;
        if (tid == 0) { s_g = 0; s_e = 0; }
        __syncthreads();
        for (int p = tid; p < NPA; p += 512) {
            unsigned bits = __float_as_uint(sc[p]);
            if (bits > V) {
                int q = atomicAdd(&s_g, 1);
                if (q < 1024)
                    keys[q] = ((unsigned long long)bits << 32) |
                              (unsigned long long)(0xFFFFFFFFu - (unsigned)p);
            } else if (bits == V) {
                int q = atomicAdd(&s_e, 1);
                if (q < 1024) eqbuf[q] = p;
            }
        }
        __syncthreads();
        int ng = s_g < 1024 ? s_g : 1024;
        int ne = s_e < 1024 ? s_e : 1024;
        for (int i = tid; i < 1024; i += 512) {
            if (i >= ng) {
                int e = i - ng;
                keys[i] = (e < ne)
                    ? (((unsigned long long)V << 32) |
                       (unsigned long long)(0xFFFFFFFFu - (unsigned)eqbuf[e]))
                    : 0ULL;
            }
        }
    }

    for (int k = 2; k <= 1024; k <<= 1)
        for (int j = k >> 1; j > 0; j >>= 1) {
            __syncthreads();
            for (int i = tid; i < 1024; i += 512) {
                int l = i ^ j;
                if (l > i) {
                    unsigned long long a = keys[i], bb = keys[l];
                    bool up = ((i & k) == 0);
                    if (up ? (a < bb) : (a > bb)) { keys[i] = bb; keys[l] = a; }
                }
            }
        }
    __syncthreads();

    for (int i = tid; i < PRE_K; i += 512) {
        unsigned long long kv = keys[i];
        unsigned bits = (unsigned)(kv >> 32);
        if (bits == 0u) { ssc[i] = 0.f; sbox[2*i] = 0.f; sbox[2*i+1] = 0.f; }
        else {
            unsigned ridx = 0xFFFFFFFFu - (unsigned)(kv & 0xFFFFFFFFull);
            ssc[i] = __uint_as_float(bits);
            const float* bp = g_boxes + ((size_t)b*NPA + ridx)*2;
            sbox[2*i] = bp[0]; sbox[2*i+1] = bp[1];
        }
    }
    __syncthreads();

    for (int i = tid; i < PRE_K; i += 512) {
        float si = sbox[2*i], ei = sbox[2*i+1], wi = ei - si;
        for (int w = 0; w < NMW; w++) {
            unsigned m = 0;
            int jb = w*32, jm = i - jb; if (jm > 32) jm = 32;
            for (int jj = 0; jj < jm; jj++) {
                int j = jb + jj;
                float sj = sbox[2*j], ej = sbox[2*j+1];
                float inter = fmaxf(fminf(ei, ej) - fmaxf(si, sj), 0.f);
                float iou = inter / fmaxf(wi + (ej - sj) - inter, 1e-6f);
                if (iou > 0.5f) m |= (1u << jj);
            }
            smask[i*NMW + w] = m;
        }
    }
    __syncthreads();

    if (tid < 32) {
        int lane = tid;
        unsigned keepw = 0;
        int nk = 0;
        for (int i = 0; i < PRE_K; i++) {
            unsigned mw = (lane < NMW) ? smask[i*NMW + lane] : 0u;
            bool sup = __any_sync(0xffffffffu, (mw & keepw) != 0u);
            bool val = (ssc[i] >= 0.1f);
            if (val && !sup) {
                if (lane == (i >> 5)) keepw |= (1u << (i & 31));
                if (lane == 0 && nk < POST_K) skept[nk] = i;
                nk++;
            }
        }
        if (lane == 0) s_nk = (nk < POST_K) ? nk : POST_K;
    }
    __syncthreads();

    int nk = s_nk;
    for (int r = tid; r < POST_K; r += 512) {
        bool on = r < nk;
        int i = on ? skept[r] : 0;
        size_t base = (size_t)b*POST_K + r;
        out[OFF_PROPS + 2*base]   = on ? sbox[2*i]   : 0.f;
        out[OFF_PROPS + 2*base+1] = on ? sbox[2*i+1] : 0.f;
        out[OFF_PSC + base]   = on ? ssc[i] : 0.f;
        out[OFF_PMASK + base] = on ? 1.0f : 0.0f;
    }
}

// ---------------------------------------------------------------------------
extern "C" void kernel_launch(void* const* d_in, const int* in_sizes, int n_in,
                              void* d_out, int out_size) {
    const float* feat   = (const float*)d_in[0];
    const float* conv_w = (const float*)d_in[1];
    const float* conv_b = (const float*)d_in[2];
    const float* obj_w  = (const float*)d_in[3];
    const float* obj_b  = (const float*)d_in[4];
    const float* reg_w  = (const float*)d_in[5];
    const float* reg_b  = (const float*)d_in[6];
    float* out = (float*)d_out;

    cudaFuncSetAttribute(conv_mma_kernel, cudaFuncAttributeMaxDynamicSharedMemorySize, CONV_SMEM);
    cudaFuncSetAttribute(topk_nms_kernel, cudaFuncAttributeMaxDynamicSharedMemorySize, TK_SMEM);

    splitw_kernel<<<(3*512*512 + 255)/256, 256>>>(conv_w);
    pad_kernel<<<NB, 512>>>();
    dim3 sgrid(NL/64, NC/64, NB);
    splitfeat_kernel<<<sgrid, 256>>>(feat);

    dim3 cgrid(NL/128, NC/128, NB);          // (64, 4, 8)
    conv_mma_kernel<<<cgrid, 256, CONV_SMEM>>>(conv_b, obj_w, reg_w);

    dim3 dgrid(NL/256, NB);
    decode_kernel<<<dgrid, 256>>>(obj_b, reg_b, out);

    anchors_kernel<<<(NPA + 255)/256, 256>>>(out);

    topk_nms_kernel<<<NB, 512, TK_SMEM>>>(out);
}

// round 12
// speedup vs baseline: 1.1950x; 1.0557x over previous
#include <cuda_runtime.h>
#include <cuda_fp16.h>
#include <math.h>
#include <stdint.h>

#define NB 8
#define NC 512
#define NL 8192
#define NA 7
#define NPA (NL*NA)
#define PRE_K 600
#define POST_K 100
#define NMW 19
#define LPAD 8194

#define OFF_OBJ  0
#define SZ_OBJ   (NB*NPA)
#define OFF_REG  (SZ_OBJ)
#define SZ_REG   (NB*NPA*2)
#define OFF_ANCH (OFF_REG + SZ_REG)
#define SZ_ANCH  (NPA*2)
#define OFF_PROPS (OFF_ANCH + SZ_ANCH)
#define SZ_PROPS (NB*POST_K*2)
#define OFF_PSC  (OFF_PROPS + SZ_PROPS)
#define OFF_PMASK (OFF_PSC + NB*POST_K)

__device__ float g_pp[(size_t)NB*4*21*NL];
__device__ float g_boxes[(size_t)NB*NPA*2];
__device__ float g_scores[(size_t)NB*NPA];
__device__ __align__(256) __half g_fT1[(size_t)NB*LPAD*NC];
__device__ __align__(256) __half g_fT2[(size_t)NB*LPAD*NC];
__device__ __align__(256) __half g_W1[3*512*512];
__device__ __align__(256) __half g_W2[3*512*512];

__constant__ float c_lens[NA] = {1.f,2.f,3.f,4.f,5.f,7.f,9.f};

__device__ __forceinline__ uint32_t smem_u32(const void* p) {
    uint32_t a;
    asm("{ .reg .u64 t; cvta.to.shared.u64 t, %1; cvt.u32.u64 %0, t; }" : "=r"(a) : "l"(p));
    return a;
}
#define CP16(dst,src) asm volatile("cp.async.cg.shared.global [%0], [%1], 16;"::"r"(dst),"l"(src))
#define CPCOMMIT() asm volatile("cp.async.commit_group;":::"memory")
#define CPWAIT1() asm volatile("cp.async.wait_group 1;":::"memory")
#define LDSM4(r,addr) asm volatile( \
    "ldmatrix.sync.aligned.m8n8.x4.shared.b16 {%0,%1,%2,%3}, [%4];" \
    : "=r"((r)[0]),"=r"((r)[1]),"=r"((r)[2]),"=r"((r)[3]) : "r"(addr))
#define MMA(d,a,b0,b1) asm volatile( \
    "mma.sync.aligned.m16n8k16.row.col.f32.f16.f16.f32 " \
    "{%0,%1,%2,%3}, {%4,%5,%6,%7}, {%8,%9}, {%0,%1,%2,%3};" \
    : "+f"((d)[0]),"+f"((d)[1]),"+f"((d)[2]),"+f"((d)[3]) \
    : "r"((a)[0]),"r"((a)[1]),"r"((a)[2]),"r"((a)[3]),"r"(b0),"r"(b1))
#define MMAH(d,a,b0,b1) asm volatile( \
    "mma.sync.aligned.m16n8k16.row.col.f16.f16.f16.f16 " \
    "{%0,%1}, {%2,%3,%4,%5}, {%6,%7}, {%0,%1};" \
    : "+r"((d)[0]),"+r"((d)[1]) \
    : "r"((a)[0]),"r"((a)[1]),"r"((a)[2]),"r"((a)[3]),"r"(b0),"r"(b1))

// ---- prep: weight split + pad rows (merged) ----
__global__ void splitw_pad_kernel(const float* __restrict__ w) {
    if (blockIdx.x >= 3072) {
        int b = blockIdx.x - 3072, c = threadIdx.x;
        if (c < 512) {
            __half z = __float2half_rn(0.f);
            size_t r0 = ((size_t)b*LPAD)*NC + c, r1 = ((size_t)b*LPAD + (LPAD-1))*NC + c;
            g_fT1[r0]=z; g_fT2[r0]=z;
            g_fT1[r1]=z; g_fT2[r1]=z;
        }
        return;
    }
    int idx = blockIdx.x*256 + threadIdx.x;
    int c = idx & 511, o = (idx >> 9) & 511, t = idx >> 18;
    float v = w[(size_t)o*1536 + c*3 + t];
    __half a1 = __float2half_rn(v);
    g_W1[idx] = a1;
    g_W2[idx] = __float2half_rn(v - __half2float(a1));
}
__global__ __launch_bounds__(256)
void splitfeat_kernel(const float* __restrict__ feat) {
    __shared__ float tile[64][65];
    int b = blockIdx.z, c0 = blockIdx.y*64, l0 = blockIdx.x*64;
    int tj = threadIdx.x & 63, ti = threadIdx.x >> 6;
    const float* src = feat + ((size_t)b*NC + c0)*NL + l0;
#pragma unroll
    for (int i = ti; i < 64; i += 4) tile[i][tj] = src[(size_t)i*NL + tj];
    __syncthreads();
#pragma unroll
    for (int lj = ti; lj < 64; lj += 4) {
        float v = tile[tj][lj];
        __half a1 = __float2half_rn(v);
        size_t dst = ((size_t)b*LPAD + (l0 + lj + 1))*NC + c0 + tj;
        g_fT1[dst] = a1;
        g_fT2[dst] = __float2half_rn(v - __half2float(a1));
    }
}

// ---- conv + fused partial projection ----
#define ROWB2   80u
#define WTILE2  10240u
#define F_OFF2  61440u
#define FTILE2  10560u
#define STG2    82560u
#define CONV_SMEM (2u*STG2)

__device__ __forceinline__ void load_stage(uint32_t sb, int s,
                                           int b, int l0, int o0, int tid) {
    const uint32_t buf = sb + (uint32_t)(s & 1)*STG2;
    const int c0 = s << 5;
#pragma unroll
    for (int i = 0; i < 12; i++) {
        int id = tid + 256*i;
        int r = id & 127, q = (id >> 7) & 3, tl = id >> 9;
        const __half* gw = (tl & 1) ? g_W2 : g_W1;
        size_t src = ((size_t)((tl>>1)*512 + o0 + r))*512 + c0 + q*8;
        CP16(buf + (uint32_t)tl*WTILE2 + (uint32_t)r*ROWB2 + q*16, gw + src);
    }
#pragma unroll
    for (int i = 0; i < 5; i++) {
        int id = tid + 256*i;
        if (id < 1040) {
            int q = id & 3, rem = id >> 2;
            int L = rem >= 130 ? 1 : 0;
            int fr = rem - L*130;
            const __half* gf = L ? g_fT2 : g_fT1;
            size_t src = ((size_t)b*LPAD + (size_t)(l0 + fr))*512 + c0 + q*8;
            CP16(buf + F_OFF2 + (uint32_t)L*FTILE2 + (uint32_t)fr*ROWB2 + q*16, gf + src);
        }
    }
}

__global__ __launch_bounds__(256, 1)
void conv_mma_kernel(const float* __restrict__ bias,
                     const float* __restrict__ obj_w,
                     const float* __restrict__ reg_w) {
    extern __shared__ char smem[];
    uint32_t sb = smem_u32(smem);
    const int tid = threadIdx.x, lane = tid & 31, w = tid >> 5;
    const int wo = w & 1, wl = w >> 1;
    const int b = blockIdx.z, ob = blockIdx.y, o0 = ob*128, l0 = blockIdx.x*128;

    float acc[4][4][4];
    uint32_t acc16[4][4][2];
#pragma unroll
    for (int i=0;i<4;i++)
#pragma unroll
        for (int j=0;j<4;j++) {
#pragma unroll
            for (int k=0;k<4;k++) acc[i][j][k]=0.f;
            acc16[i][j][0]=0u; acc16[i][j][1]=0u;
        }

    load_stage(sb, 0, b, l0, o0, tid); CPCOMMIT();
    load_stage(sb, 1, b, l0, o0, tid); CPCOMMIT();

    const int lr = lane & 15, lc16 = (lane >> 4) * 16;

    for (int s = 0; s < 16; s++) {
        CPWAIT1();
        __syncthreads();
        const uint32_t buf = sb + (uint32_t)(s & 1)*STG2;
#pragma unroll
        for (int t = 0; t < 3; t++) {
#pragma unroll
            for (int kk = 0; kk < 2; kk++) {
                const uint32_t ko = (uint32_t)(kk*32) + lc16;
                uint32_t a1[4][4], a2[4][4], b1[2][4], b2[2][4];
#pragma unroll
                for (int mt = 0; mt < 4; mt++) {
                    uint32_t r = (uint32_t)(wo*64 + mt*16 + lr)*ROWB2 + ko;
                    LDSM4(a1[mt], buf + (uint32_t)(t*2)*WTILE2 + r);
                    LDSM4(a2[mt], buf + (uint32_t)(t*2+1)*WTILE2 + r);
                }
#pragma unroll
                for (int nt = 0; nt < 2; nt++) {
                    uint32_t r = (uint32_t)(wl*32 + nt*16 + lr + t)*ROWB2 + ko;
                    LDSM4(b1[nt], buf + F_OFF2 + r);
                    LDSM4(b2[nt], buf + F_OFF2 + FTILE2 + r);
                }
#pragma unroll
                for (int mt = 0; mt < 4; mt++)
#pragma unroll
                for (int nt = 0; nt < 2; nt++) {
                    MMA(acc[mt][2*nt],   a1[mt], b1[nt][0], b1[nt][2]);
                    MMA(acc[mt][2*nt+1], a1[mt], b1[nt][1], b1[nt][3]);
                }
#pragma unroll
                for (int mt = 0; mt < 4; mt++)
#pragma unroll
                for (int nt = 0; nt < 2; nt++) {
                    MMAH(acc16[mt][2*nt],   a1[mt], b2[nt][0], b2[nt][2]);
                    MMAH(acc16[mt][2*nt+1], a1[mt], b2[nt][1], b2[nt][3]);
                    MMAH(acc16[mt][2*nt],   a2[mt], b1[nt][0], b1[nt][2]);
                    MMAH(acc16[mt][2*nt+1], a2[mt], b1[nt][1], b1[nt][3]);
                }
            }
        }
        __syncthreads();
        if (s + 2 < 16) { load_stage(sb, s+2, b, l0, o0, tid); }
        CPCOMMIT();
    }

    // ---- fused epilogue: h tile -> smem, then vectorized 21-ch projection ----
    __syncthreads();
    float* hs = (float*)smem;                      // [128][132]
    float* w21 = hs + 128*132;                     // [21][128]
    const int r0 = lane >> 2, cp = (lane & 3)*2;
#pragma unroll
    for (int mt = 0; mt < 4; mt++) {
        int orow0 = wo*64 + mt*16 + r0;
        float bv0 = __ldg(bias + o0 + orow0), bv1 = __ldg(bias + o0 + orow0 + 8);
#pragma unroll
        for (int nb = 0; nb < 4; nb++) {
            int lc = wl*32 + nb*8 + cp;
            __half2 x0 = *(__half2*)&acc16[mt][nb][0];
            __half2 x1 = *(__half2*)&acc16[mt][nb][1];
            hs[orow0*132 + lc]       = fmaxf(acc[mt][nb][0] + __half2float(x0.x) + bv0, 0.f);
            hs[orow0*132 + lc + 1]   = fmaxf(acc[mt][nb][1] + __half2float(x0.y) + bv0, 0.f);
            hs[(orow0+8)*132 + lc]   = fmaxf(acc[mt][nb][2] + __half2float(x1.x) + bv1, 0.f);
            hs[(orow0+8)*132 + lc+1] = fmaxf(acc[mt][nb][3] + __half2float(x1.y) + bv1, 0.f);
        }
    }
    for (int i = tid; i < 21*128; i += 256) {
        int a = i >> 7, o = i & 127;
        w21[i] = (a < 7) ? __ldg(obj_w + a*512 + o0 + o)
                         : __ldg(reg_w + (a-7)*512 + o0 + o);
    }
    __syncthreads();

    float* pp = g_pp + (((size_t)b*4 + ob)*21)*NL + l0;
    for (int i = tid; i < 21*32; i += 256) {
        int a = i >> 5, l4 = (i & 31)*4;
        float4 s4 = make_float4(0.f, 0.f, 0.f, 0.f);
        const float* wr = w21 + a*128;
#pragma unroll 8
        for (int o = 0; o < 128; o++) {
            float wv = wr[o];
            float4 h4 = *(float4*)(hs + o*132 + l4);
            s4.x += wv*h4.x; s4.y += wv*h4.y; s4.z += wv*h4.z; s4.w += wv*h4.w;
        }
        *(float4*)(pp + (size_t)a*NL + l4) = s4;
    }
}

// ---- decode (+ anchors for b==0) ----
__global__ __launch_bounds__(256)
void decode_kernel(const float* __restrict__ obj_b,
                   const float* __restrict__ reg_b,
                   float* __restrict__ out) {
    const int b = blockIdx.y;
    const int l = blockIdx.x*256 + threadIdx.x;
    const float* pb = g_pp + ((size_t)b*4*21)*NL + l;

    float sv[21];
#pragma unroll
    for (int a = 0; a < 21; a++) {
        float s0 = pb[(size_t)a*NL];
        s0 += pb[(size_t)(21 + a)*NL];
        s0 += pb[(size_t)(42 + a)*NL];
        s0 += pb[(size_t)(63 + a)*NL];
        sv[a] = s0;
    }
#pragma unroll
    for (int a = 0; a < NA; a++) {
        float ol = sv[a] + __ldg(obj_b + a);
        size_t n = (size_t)b*NPA + (size_t)l*NA + a;
        out[OFF_OBJ + n] = ol;
        g_scores[n] = 1.f/(1.f + expf(-ol));
        float tc = sv[7+2*a]   + __ldg(reg_b + 2*a);
        float tw = sv[7+2*a+1] + __ldg(reg_b + 2*a+1);
        out[OFF_REG + 2*n] = tc; out[OFF_REG + 2*n+1] = tw;
        float len = c_lens[a];
        float twc = fminf(fmaxf(tw, -10.f), 10.f);
        float cc = ((float)l + 0.5f) + tc*len;
        float ww = len * expf(twc);
        float s = fminf(fmaxf(cc - 0.5f*ww, 0.f), 8192.f);
        float e = fminf(fmaxf(cc + 0.5f*ww, 0.f), 8192.f);
        e = fminf(fmaxf(e, s + 1e-3f), 8192.f);
        s = fmaxf(fminf(s, e - 1e-3f), 0.f);
        g_boxes[2*n] = s; g_boxes[2*n+1] = e;
        if (b == 0) {
            float cen = (float)l + 0.5f, half = 0.5f*len;
            size_t m = (size_t)l*NA + a;
            out[OFF_ANCH + 2*m]     = cen - half;
            out[OFF_ANCH + 2*m + 1] = cen + half;
        }
    }
}

// ---- topk + NMS ----
#define TK_SMEM 65536
__global__ __launch_bounds__(512)
void topk_nms_kernel(float* __restrict__ out) {
    extern __shared__ char dynsm[];
    int* hist = (int*)dynsm;
    unsigned long long* keys = (unsigned long long*)dynsm;
    unsigned* smask = (unsigned*)(dynsm + 8192);
    int* eqbuf = (int*)(dynsm + 57344);
    __shared__ float sbox[PRE_K*2];
    __shared__ float ssc[PRE_K];
    __shared__ int skept[POST_K];
    __shared__ int csum[512];
    __shared__ int s_cnt, s_g, s_e, s_nk, s_B, s_ncand;

    const int b = blockIdx.x, tid = threadIdx.x;
    const float* sc = g_scores + (size_t)b*NPA;

    for (int i = tid; i < 16384; i += 512) hist[i] = 0;
    __syncthreads();
    for (int p = tid; p < NPA; p += 512)
        atomicAdd(&hist[__float_as_uint(sc[p]) >> 16], 1);
    __syncthreads();
    int cs = 0;
#pragma unroll 8
    for (int j = 0; j < 32; j++) cs += hist[tid*32 + j];
    csum[tid] = cs;
    __syncthreads();
    if (tid == 0) {
        int acc = 0, tc = 511;
        for (; tc > 0; tc--) { if (acc + csum[tc] >= PRE_K) break; acc += csum[tc]; }
        int B = tc*32;
        for (int j = tc*32 + 31; j >= tc*32; j--) {
            if (acc + hist[j] >= PRE_K) { B = j; break; }
            acc += hist[j];
        }
        s_B = B; s_ncand = acc + hist[B];
    }
    __syncthreads();
    const int B = s_B;
    const int ncand = s_ncand;

    if (ncand <= 1024) {
        if (tid == 0) s_g = 0;
        __syncthreads();
        for (int p = tid; p < NPA; p += 512) {
            unsigned bits = __float_as_uint(sc[p]);
            if ((int)(bits >> 16) >= B) {
                int q = atomicAdd(&s_g, 1);
                keys[q] = ((unsigned long long)bits << 32) |
                          (unsigned long long)(0xFFFFFFFFu - (unsigned)p);
            }
        }
        __syncthreads();
        for (int i = tid + ncand; i < 1024; i += 512) keys[i] = 0ULL;
    } else {
        unsigned lo = (unsigned)B << 16, hi = ((unsigned)B << 16) + 0x10000u;
        for (int it = 0; it < 17 && (hi - lo) > 1u; ++it) {
            unsigned mid = lo + ((hi - lo) >> 1);
            if (tid == 0) s_cnt = 0;
            __syncthreads();
            int c = 0;
            for (int p = tid; p < NPA; p += 512)
                c += (__float_as_uint(sc[p]) >= mid) ? 1 : 0;
#pragma unroll
            for (int o = 16; o; o >>= 1) c += __shfl_down_sync(0xffffffffu, c, o);
            if ((tid & 31) == 0) atomicAdd(&s_cnt, c);
            __syncthreads();
            if (s_cnt >= PRE_K) lo = mid; else hi = mid;
            __syncthreads();
        }
        unsigned V = lo;
        if (tid == 0) { s_g = 0; s_e = 0; }
        __syncthreads();
        for (int p = tid; p < NPA; p += 512) {
            unsigned bits = __float_as_uint(sc[p]);
            if (bits > V) {
                int q = atomicAdd(&s_g, 1);
                if (q < 1024)
                    keys[q] = ((unsigned long long)bits << 32) |
                              (unsigned long long)(0xFFFFFFFFu - (unsigned)p);
            } else if (bits == V) {
                int q = atomicAdd(&s_e, 1);
                if (q < 1024) eqbuf[q] = p;
            }
        }
        __syncthreads();
        int ng = s_g < 1024 ? s_g : 1024;
        int ne = s_e < 1024 ? s_e : 1024;
        for (int i = tid; i < 1024; i += 512) {
            if (i >= ng) {
                int e = i - ng;
                keys[i] = (e < ne)
                    ? (((unsigned long long)V << 32) |
                       (unsigned long long)(0xFFFFFFFFu - (unsigned)eqbuf[e]))
                    : 0ULL;
            }
        }
    }

    for (int k = 2; k <= 1024; k <<= 1)
        for (int j = k >> 1; j > 0; j >>= 1) {
            __syncthreads();
            for (int i = tid; i < 1024; i += 512) {
                int l = i ^ j;
                if (l > i) {
                    unsigned long long a = keys[i], bb = keys[l];
                    bool up = ((i & k) == 0);
                    if (up ? (a < bb) : (a > bb)) { keys[i] = bb; keys[l] = a; }
                }
            }
        }
    __syncthreads();

    for (int i = tid; i < PRE_K; i += 512) {
        unsigned long long kv = keys[i];
        unsigned bits = (unsigned)(kv >> 32);
        if (bits == 0u) { ssc[i] = 0.f; sbox[2*i] = 0.f; sbox[2*i+1] = 0.f; }
        else {
            unsigned ridx = 0xFFFFFFFFu - (unsigned)(kv & 0xFFFFFFFFull);
            ssc[i] = __uint_as_float(bits);
            const float* bp = g_boxes + ((size_t)b*NPA + ridx)*2;
            sbox[2*i] = bp[0]; sbox[2*i+1] = bp[1];
        }
    }
    __syncthreads();

    for (int i = tid; i < PRE_K; i += 512) {
        float si = sbox[2*i], ei = sbox[2*i+1], wi = ei - si;
        for (int w = 0; w < NMW; w++) {
            unsigned m = 0;
            int jb = w*32, jm = i - jb; if (jm > 32) jm = 32;
            for (int jj = 0; jj < jm; jj++) {
                int j = jb + jj;
                float sj = sbox[2*j], ej = sbox[2*j+1];
                float inter = fmaxf(fminf(ei, ej) - fmaxf(si, sj), 0.f);
                float iou = inter / fmaxf(wi + (ej - sj) - inter, 1e-6f);
                if (iou > 0.5f) m |= (1u << jj);
            }
            smask[i*NMW + w] = m;
        }
    }
    __syncthreads();

    if (tid < 32) {
        int lane = tid;
        unsigned keepw = 0;
        int nk = 0;
        for (int i = 0; i < PRE_K && nk < POST_K; i++) {
            unsigned mw = (lane < NMW) ? smask[i*NMW + lane] : 0u;
            bool sup = __any_sync(0xffffffffu, (mw & keepw) != 0u);
            bool val = (ssc[i] >= 0.1f);
            if (val && !sup) {
                if (lane == (i >> 5)) keepw |= (1u << (i & 31));
                if (lane == 0) skept[nk] = i;
                nk++;
            }
        }
        if (lane == 0) s_nk = nk;
    }
    __syncthreads();

    int nk = s_nk;
    for (int r = tid; r < POST_K; r += 512) {
        bool on = r < nk;
        int i = on ? skept[r] : 0;
        size_t base = (size_t)b*POST_K + r;
        out[OFF_PROPS + 2*base]   = on ? sbox[2*i]   : 0.f;
        out[OFF_PROPS + 2*base+1] = on ? sbox[2*i+1] : 0.f;
        out[OFF_PSC + base]   = on ? ssc[i] : 0.f;
        out[OFF_PMASK + base] = on ? 1.0f : 0.0f;
    }
}

// ---------------------------------------------------------------------------
extern "C" void kernel_launch(void* const* d_in, const int* in_sizes, int n_in,
                              void* d_out, int out_size) {
    const float* feat   = (const float*)d_in[0];
    const float* conv_w = (const float*)d_in[1];
    const float* conv_b = (const float*)d_in[2];
    const float* obj_w  = (const float*)d_in[3];
    const float* obj_b  = (const float*)d_in[4];
    const float* reg_w  = (const float*)d_in[5];
    const float* reg_b  = (const float*)d_in[6];
    float* out = (float*)d_out;

    cudaFuncSetAttribute(conv_mma_kernel, cudaFuncAttributeMaxDynamicSharedMemorySize, CONV_SMEM);
    cudaFuncSetAttribute(topk_nms_kernel, cudaFuncAttributeMaxDynamicSharedMemorySize, TK_SMEM);

    splitw_pad_kernel<<<3072 + NB, 256>>>(conv_w);
    dim3 sgrid(NL/64, NC/64, NB);
    splitfeat_kernel<<<sgrid, 256>>>(feat);

    dim3 cgrid(NL/128, NC/128, NB);          // (64, 4, 8)
    conv_mma_kernel<<<cgrid, 256, CONV_SMEM>>>(conv_b, obj_w, reg_w);

    dim3 dgrid(NL/256, NB);
    decode_kernel<<<dgrid, 256>>>(obj_b, reg_b, out);

    topk_nms_kernel<<<NB, 512, TK_SMEM>>>(out);
}

// round 13
// speedup vs baseline: 1.2012x; 1.0052x over previous
#include <cuda_runtime.h>
#include <cuda_fp16.h>
#include <math.h>
#include <stdint.h>

#define NB 8
#define NC 512
#define NL 8192
#define NA 7
#define NPA (NL*NA)
#define PRE_K 600
#define POST_K 100
#define NMW 19
#define LPAD 8194

#define OFF_OBJ  0
#define SZ_OBJ   (NB*NPA)
#define OFF_REG  (SZ_OBJ)
#define SZ_REG   (NB*NPA*2)
#define OFF_ANCH (OFF_REG + SZ_REG)
#define SZ_ANCH  (NPA*2)
#define OFF_PROPS (OFF_ANCH + SZ_ANCH)
#define SZ_PROPS (NB*POST_K*2)
#define OFF_PSC  (OFF_PROPS + SZ_PROPS)
#define OFF_PMASK (OFF_PSC + NB*POST_K)

__device__ float g_pp[(size_t)NB*4*21*NL];
__device__ float g_boxes[(size_t)NB*NPA*2];
__device__ float g_scores[(size_t)NB*NPA];
__device__ __align__(256) __half g_fT1[(size_t)NB*LPAD*NC];
__device__ __align__(256) __half g_fT2[(size_t)NB*LPAD*NC];
__device__ __align__(256) __half g_W1[3*512*512];
__device__ __align__(256) __half g_W2[3*512*512];

__constant__ float c_lens[NA] = {1.f,2.f,3.f,4.f,5.f,7.f,9.f};

__device__ __forceinline__ uint32_t smem_u32(const void* p) {
    uint32_t a;
    asm("{ .reg .u64 t; cvta.to.shared.u64 t, %1; cvt.u32.u64 %0, t; }" : "=r"(a) : "l"(p));
    return a;
}
#define CP16(dst,src) asm volatile("cp.async.cg.shared.global [%0], [%1], 16;"::"r"(dst),"l"(src))
#define CPCOMMIT() asm volatile("cp.async.commit_group;":::"memory")
#define CPWAIT1() asm volatile("cp.async.wait_group 1;":::"memory")
#define LDSM4(r,addr) asm volatile( \
    "ldmatrix.sync.aligned.m8n8.x4.shared.b16 {%0,%1,%2,%3}, [%4];" \
    : "=r"((r)[0]),"=r"((r)[1]),"=r"((r)[2]),"=r"((r)[3]) : "r"(addr))
#define MMA(d,a,b0,b1) asm volatile( \
    "mma.sync.aligned.m16n8k16.row.col.f32.f16.f16.f32 " \
    "{%0,%1,%2,%3}, {%4,%5,%6,%7}, {%8,%9}, {%0,%1,%2,%3};" \
    : "+f"((d)[0]),"+f"((d)[1]),"+f"((d)[2]),"+f"((d)[3]) \
    : "r"((a)[0]),"r"((a)[1]),"r"((a)[2]),"r"((a)[3]),"r"(b0),"r"(b1))
#define MMAH(d,a,b0,b1) asm volatile( \
    "mma.sync.aligned.m16n8k16.row.col.f16.f16.f16.f16 " \
    "{%0,%1}, {%2,%3,%4,%5}, {%6,%7}, {%0,%1};" \
    : "+r"((d)[0]),"+r"((d)[1]) \
    : "r"((a)[0]),"r"((a)[1]),"r"((a)[2]),"r"((a)[3]),"r"(b0),"r"(b1))

// ---- prep: weight split + pad rows (merged) ----
__global__ void splitw_pad_kernel(const float* __restrict__ w) {
    if (blockIdx.x >= 3072) {
        int b = blockIdx.x - 3072, c = threadIdx.x;
        if (c < 512) {
            __half z = __float2half_rn(0.f);
            size_t r0 = ((size_t)b*LPAD)*NC + c, r1 = ((size_t)b*LPAD + (LPAD-1))*NC + c;
            g_fT1[r0]=z; g_fT2[r0]=z;
            g_fT1[r1]=z; g_fT2[r1]=z;
        }
        return;
    }
    int idx = blockIdx.x*256 + threadIdx.x;
    int c = idx & 511, o = (idx >> 9) & 511, t = idx >> 18;
    float v = w[(size_t)o*1536 + c*3 + t];
    __half a1 = __float2half_rn(v);
    g_W1[idx] = a1;
    g_W2[idx] = __float2half_rn(v - __half2float(a1));
}
__global__ __launch_bounds__(256)
void splitfeat_kernel(const float* __restrict__ feat) {
    __shared__ float tile[64][65];
    int b = blockIdx.z, c0 = blockIdx.y*64, l0 = blockIdx.x*64;
    int tj = threadIdx.x & 63, ti = threadIdx.x >> 6;
    const float* src = feat + ((size_t)b*NC + c0)*NL + l0;
#pragma unroll
    for (int i = ti; i < 64; i += 4) tile[i][tj] = src[(size_t)i*NL + tj];
    __syncthreads();
#pragma unroll
    for (int lj = ti; lj < 64; lj += 4) {
        float v = tile[tj][lj];
        __half a1 = __float2half_rn(v);
        size_t dst = ((size_t)b*LPAD + (l0 + lj + 1))*NC + c0 + tj;
        g_fT1[dst] = a1;
        g_fT2[dst] = __float2half_rn(v - __half2float(a1));
    }
}

// ---- conv + fused partial projection ----
#define ROWB2   80u
#define WTILE2  10240u
#define F_OFF2  61440u
#define FTILE2  10560u
#define STG2    82560u
#define CONV_SMEM (2u*STG2)

__device__ __forceinline__ void load_stage(uint32_t sb, int s,
                                           int b, int l0, int o0, int tid) {
    const uint32_t buf = sb + (uint32_t)(s & 1)*STG2;
    const int c0 = s << 5;
#pragma unroll
    for (int i = 0; i < 12; i++) {
        int id = tid + 256*i;
        int r = id & 127, q = (id >> 7) & 3, tl = id >> 9;
        const __half* gw = (tl & 1) ? g_W2 : g_W1;
        size_t src = ((size_t)((tl>>1)*512 + o0 + r))*512 + c0 + q*8;
        CP16(buf + (uint32_t)tl*WTILE2 + (uint32_t)r*ROWB2 + q*16, gw + src);
    }
#pragma unroll
    for (int i = 0; i < 5; i++) {
        int id = tid + 256*i;
        if (id < 1040) {
            int q = id & 3, rem = id >> 2;
            int L = rem >= 130 ? 1 : 0;
            int fr = rem - L*130;
            const __half* gf = L ? g_fT2 : g_fT1;
            size_t src = ((size_t)b*LPAD + (size_t)(l0 + fr))*512 + c0 + q*8;
            CP16(buf + F_OFF2 + (uint32_t)L*FTILE2 + (uint32_t)fr*ROWB2 + q*16, gf + src);
        }
    }
}

__global__ __launch_bounds__(256, 1)
void conv_mma_kernel(const float* __restrict__ bias,
                     const float* __restrict__ obj_w,
                     const float* __restrict__ reg_w) {
    extern __shared__ char smem[];
    uint32_t sb = smem_u32(smem);
    const int tid = threadIdx.x, lane = tid & 31, w = tid >> 5;
    const int wo = w & 1, wl = w >> 1;
    const int b = blockIdx.z, ob = blockIdx.x, o0 = ob*128, l0 = blockIdx.y*128;

    float acc[4][4][4];
    uint32_t acc16[4][4][2];
#pragma unroll
    for (int i=0;i<4;i++)
#pragma unroll
        for (int j=0;j<4;j++) {
#pragma unroll
            for (int k=0;k<4;k++) acc[i][j][k]=0.f;
            acc16[i][j][0]=0u; acc16[i][j][1]=0u;
        }

    load_stage(sb, 0, b, l0, o0, tid); CPCOMMIT();
    load_stage(sb, 1, b, l0, o0, tid); CPCOMMIT();

    const int lr = lane & 15, lc16 = (lane >> 4) * 16;

    for (int s = 0; s < 16; s++) {
        CPWAIT1();
        __syncthreads();
        const uint32_t buf = sb + (uint32_t)(s & 1)*STG2;
#pragma unroll
        for (int t = 0; t < 3; t++) {
#pragma unroll
            for (int kk = 0; kk < 2; kk++) {
                const uint32_t ko = (uint32_t)(kk*32) + lc16;
                uint32_t a1[4][4], a2[4][4], b1[2][4], b2[2][4];
#pragma unroll
                for (int mt = 0; mt < 4; mt++) {
                    uint32_t r = (uint32_t)(wo*64 + mt*16 + lr)*ROWB2 + ko;
                    LDSM4(a1[mt], buf + (uint32_t)(t*2)*WTILE2 + r);
                    LDSM4(a2[mt], buf + (uint32_t)(t*2+1)*WTILE2 + r);
                }
#pragma unroll
                for (int nt = 0; nt < 2; nt++) {
                    uint32_t r = (uint32_t)(wl*32 + nt*16 + lr + t)*ROWB2 + ko;
                    LDSM4(b1[nt], buf + F_OFF2 + r);
                    LDSM4(b2[nt], buf + F_OFF2 + FTILE2 + r);
                }
#pragma unroll
                for (int mt = 0; mt < 4; mt++)
#pragma unroll
                for (int nt = 0; nt < 2; nt++) {
                    MMA(acc[mt][2*nt],   a1[mt], b1[nt][0], b1[nt][2]);
                    MMA(acc[mt][2*nt+1], a1[mt], b1[nt][1], b1[nt][3]);
                }
#pragma unroll
                for (int mt = 0; mt < 4; mt++)
#pragma unroll
                for (int nt = 0; nt < 2; nt++) {
                    MMAH(acc16[mt][2*nt],   a1[mt], b2[nt][0], b2[nt][2]);
                    MMAH(acc16[mt][2*nt+1], a1[mt], b2[nt][1], b2[nt][3]);
                    MMAH(acc16[mt][2*nt],   a2[mt], b1[nt][0], b1[nt][2]);
                    MMAH(acc16[mt][2*nt+1], a2[mt], b1[nt][1], b1[nt][3]);
                }
            }
        }
        __syncthreads();
        if (s + 2 < 16) { load_stage(sb, s+2, b, l0, o0, tid); }
        CPCOMMIT();
    }

    // ---- fused epilogue: h tile -> smem, then vectorized 21-ch projection ----
    __syncthreads();
    float* hs = (float*)smem;                      // [128][132]
    float* w21 = hs + 128*132;                     // [21][128]
    const int r0 = lane >> 2, cp = (lane & 3)*2;
#pragma unroll
    for (int mt = 0; mt < 4; mt++) {
        int orow0 = wo*64 + mt*16 + r0;
        float bv0 = __ldg(bias + o0 + orow0), bv1 = __ldg(bias + o0 + orow0 + 8);
#pragma unroll
        for (int nb = 0; nb < 4; nb++) {
            int lc = wl*32 + nb*8 + cp;
            __half2 x0 = *(__half2*)&acc16[mt][nb][0];
            __half2 x1 = *(__half2*)&acc16[mt][nb][1];
            hs[orow0*132 + lc]       = fmaxf(acc[mt][nb][0] + __half2float(x0.x) + bv0, 0.f);
            hs[orow0*132 + lc + 1]   = fmaxf(acc[mt][nb][1] + __half2float(x0.y) + bv0, 0.f);
            hs[(orow0+8)*132 + lc]   = fmaxf(acc[mt][nb][2] + __half2float(x1.x) + bv1, 0.f);
            hs[(orow0+8)*132 + lc+1] = fmaxf(acc[mt][nb][3] + __half2float(x1.y) + bv1, 0.f);
        }
    }
    for (int i = tid; i < 21*128; i += 256) {
        int a = i >> 7, o = i & 127;
        w21[i] = (a < 7) ? __ldg(obj_w + a*512 + o0 + o)
                         : __ldg(reg_w + (a-7)*512 + o0 + o);
    }
    __syncthreads();

    float* pp = g_pp + (((size_t)b*4 + ob)*21)*NL + l0;
    for (int i = tid; i < 21*32; i += 256) {
        int a = i >> 5, l4 = (i & 31)*4;
        float4 s4 = make_float4(0.f, 0.f, 0.f, 0.f);
        const float* wr = w21 + a*128;
#pragma unroll 8
        for (int o = 0; o < 128; o++) {
            float wv = wr[o];
            float4 h4 = *(float4*)(hs + o*132 + l4);
            s4.x += wv*h4.x; s4.y += wv*h4.y; s4.z += wv*h4.z; s4.w += wv*h4.w;
        }
        *(float4*)(pp + (size_t)a*NL + l4) = s4;
    }
}

// ---- decode: one thread per (l, a) ----
__global__ __launch_bounds__(256)
void decode_kernel(const float* __restrict__ obj_b,
                   const float* __restrict__ reg_b,
                   float* __restrict__ out) {
    const int b = blockIdx.y;
    const int idx = blockIdx.x*256 + threadIdx.x;   // a*NL + l
    const int a = idx >> 13, l = idx & (NL-1);
    const float* pb = g_pp + ((size_t)b*4*21)*NL + l;

    float s_obj = pb[(size_t)a*NL] + pb[(size_t)(21+a)*NL]
                + pb[(size_t)(42+a)*NL] + pb[(size_t)(63+a)*NL];
    int ra = 7 + 2*a;
    float t_c = pb[(size_t)ra*NL] + pb[(size_t)(21+ra)*NL]
              + pb[(size_t)(42+ra)*NL] + pb[(size_t)(63+ra)*NL];
    float t_w = pb[(size_t)(ra+1)*NL] + pb[(size_t)(21+ra+1)*NL]
              + pb[(size_t)(42+ra+1)*NL] + pb[(size_t)(63+ra+1)*NL];

    float ol = s_obj + __ldg(obj_b + a);
    size_t n = (size_t)b*NPA + (size_t)l*NA + a;
    out[OFF_OBJ + n] = ol;
    g_scores[n] = 1.f/(1.f + expf(-ol));
    float tc = t_c + __ldg(reg_b + 2*a);
    float tw = t_w + __ldg(reg_b + 2*a+1);
    out[OFF_REG + 2*n] = tc; out[OFF_REG + 2*n+1] = tw;
    float len = c_lens[a];
    float twc = fminf(fmaxf(tw, -10.f), 10.f);
    float cc = ((float)l + 0.5f) + tc*len;
    float ww = len * expf(twc);
    float s = fminf(fmaxf(cc - 0.5f*ww, 0.f), 8192.f);
    float e = fminf(fmaxf(cc + 0.5f*ww, 0.f), 8192.f);
    e = fminf(fmaxf(e, s + 1e-3f), 8192.f);
    s = fmaxf(fminf(s, e - 1e-3f), 0.f);
    g_boxes[2*n] = s; g_boxes[2*n+1] = e;
    if (b == 0) {
        float cen = (float)l + 0.5f, half = 0.5f*len;
        size_t m = (size_t)l*NA + a;
        out[OFF_ANCH + 2*m]     = cen - half;
        out[OFF_ANCH + 2*m + 1] = cen + half;
    }
}

// ---- topk + NMS ----
#define TK_SMEM 65536
__global__ __launch_bounds__(512)
void topk_nms_kernel(float* __restrict__ out) {
    extern __shared__ char dynsm[];
    int* hist = (int*)dynsm;
    unsigned long long* keys = (unsigned long long*)dynsm;
    unsigned* smask = (unsigned*)(dynsm + 8192);
    int* eqbuf = (int*)(dynsm + 57344);
    __shared__ float sbox[PRE_K*2];
    __shared__ float ssc[PRE_K];
    __shared__ int skept[POST_K];
    __shared__ int csum[512];
    __shared__ int s_cnt, s_g, s_e, s_nk, s_B, s_ncand;

    const int b = blockIdx.x, tid = threadIdx.x;
    const float* sc = g_scores + (size_t)b*NPA;

    for (int i = tid; i < 16384; i += 512) hist[i] = 0;
    __syncthreads();
    for (int p = tid; p < NPA; p += 512)
        atomicAdd(&hist[__float_as_uint(sc[p]) >> 16], 1);
    __syncthreads();
    int cs = 0;
#pragma unroll 8
    for (int j = 0; j < 32; j++) cs += hist[tid*32 + j];
    csum[tid] = cs;
    __syncthreads();
    if (tid == 0) {
        int acc = 0, tc = 511;
        for (; tc > 0; tc--) { if (acc + csum[tc] >= PRE_K) break; acc += csum[tc]; }
        int B = tc*32;
        for (int j = tc*32 + 31; j >= tc*32; j--) {
            if (acc + hist[j] >= PRE_K) { B = j; break; }
            acc += hist[j];
        }
        s_B = B; s_ncand = acc + hist[B];
    }
    __syncthreads();
    const int B = s_B;
    const int ncand = s_ncand;

    if (ncand <= 1024) {
        if (tid == 0) s_g = 0;
        __syncthreads();
        for (int p = tid; p < NPA; p += 512) {
            unsigned bits = __float_as_uint(sc[p]);
            if ((int)(bits >> 16) >= B) {
                int q = atomicAdd(&s_g, 1);
                keys[q] = ((unsigned long long)bits << 32) |
                          (unsigned long long)(0xFFFFFFFFu - (unsigned)p);
            }
        }
        __syncthreads();
        for (int i = tid + ncand; i < 1024; i += 512) keys[i] = 0ULL;
    } else {
        unsigned lo = (unsigned)B << 16, hi = ((unsigned)B << 16) + 0x10000u;
        for (int it = 0; it < 17 && (hi - lo) > 1u; ++it) {
            unsigned mid = lo + ((hi - lo) >> 1);
            if (tid == 0) s_cnt = 0;
            __syncthreads();
            int c = 0;
            for (int p = tid; p < NPA; p += 512)
                c += (__float_as_uint(sc[p]) >= mid) ? 1 : 0;
#pragma unroll
            for (int o = 16; o; o >>= 1) c += __shfl_down_sync(0xffffffffu, c, o);
            if ((tid & 31) == 0) atomicAdd(&s_cnt, c);
            __syncthreads();
            if (s_cnt >= PRE_K) lo = mid; else hi = mid;
            __syncthreads();
        }
        unsigned V = lo;
        if (tid == 0) { s_g = 0; s_e = 0; }
        __syncthreads();
        for (int p = tid; p < NPA; p += 512) {
            unsigned bits = __float_as_uint(sc[p]);
            if (bits > V) {
                int q = atomicAdd(&s_g, 1);
                if (q < 1024)
                    keys[q] = ((unsigned long long)bits << 32) |
                              (unsigned long long)(0xFFFFFFFFu - (unsigned)p);
            } else if (bits == V) {
                int q = atomicAdd(&s_e, 1);
                if (q < 1024) eqbuf[q] = p;
            }
        }
        __syncthreads();
        int ng = s_g < 1024 ? s_g : 1024;
        int ne = s_e < 1024 ? s_e : 1024;
        for (int i = tid; i < 1024; i += 512) {
            if (i >= ng) {
                int e = i - ng;
                keys[i] = (e < ne)
                    ? (((unsigned long long)V << 32) |
                       (unsigned long long)(0xFFFFFFFFu - (unsigned)eqbuf[e]))
                    : 0ULL;
            }
        }
    }

    for (int k = 2; k <= 1024; k <<= 1)
        for (int j = k >> 1; j > 0; j >>= 1) {
            __syncthreads();
            for (int i = tid; i < 1024; i += 512) {
                int l = i ^ j;
                if (l > i) {
                    unsigned long long a = keys[i], bb = keys[l];
                    bool up = ((i & k) == 0);
                    if (up ? (a < bb) : (a > bb)) { keys[i] = bb; keys[l] = a; }
                }
            }
        }
    __syncthreads();

    for (int i = tid; i < PRE_K; i += 512) {
        unsigned long long kv = keys[i];
        unsigned bits = (unsigned)(kv >> 32);
        if (bits == 0u) { ssc[i] = 0.f; sbox[2*i] = 0.f; sbox[2*i+1] = 0.f; }
        else {
            unsigned ridx = 0xFFFFFFFFu - (unsigned)(kv & 0xFFFFFFFFull);
            ssc[i] = __uint_as_float(bits);
            const float* bp = g_boxes + ((size_t)b*NPA + ridx)*2;
            sbox[2*i] = bp[0]; sbox[2*i+1] = bp[1];
        }
    }
    __syncthreads();

    for (int i = tid; i < PRE_K; i += 512) {
        float si = sbox[2*i], ei = sbox[2*i+1], wi = ei - si;
        for (int w = 0; w < NMW; w++) {
            unsigned m = 0;
            int jb = w*32, jm = i - jb; if (jm > 32) jm = 32;
            for (int jj = 0; jj < jm; jj++) {
                int j = jb + jj;
                float sj = sbox[2*j], ej = sbox[2*j+1];
                float inter = fmaxf(fminf(ei, ej) - fmaxf(si, sj), 0.f);
                float iou = inter / fmaxf(wi + (ej - sj) - inter, 1e-6f);
                if (iou > 0.5f) m |= (1u << jj);
            }
            smask[i*NMW + w] = m;
        }
    }
    __syncthreads();

    if (tid < 32) {
        int lane = tid;
        unsigned keepw = 0;
        int nk = 0;
        for (int i = 0; i < PRE_K && nk < POST_K; i++) {
            unsigned mw = (lane < NMW) ? smask[i*NMW + lane] : 0u;
            bool sup = __any_sync(0xffffffffu, (mw & keepw) != 0u);
            bool val = (ssc[i] >= 0.1f);
            if (val && !sup) {
                if (lane == (i >> 5)) keepw |= (1u << (i & 31));
                if (lane == 0) skept[nk] = i;
                nk++;
            }
        }
        if (lane == 0) s_nk = nk;
    }
    __syncthreads();

    int nk = s_nk;
    for (int r = tid; r < POST_K; r += 512) {
        bool on = r < nk;
        int i = on ? skept[r] : 0;
        size_t base = (size_t)b*POST_K + r;
        out[OFF_PROPS + 2*base]   = on ? sbox[2*i]   : 0.f;
        out[OFF_PROPS + 2*base+1] = on ? sbox[2*i+1] : 0.f;
        out[OFF_PSC + base]   = on ? ssc[i] : 0.f;
        out[OFF_PMASK + base] = on ? 1.0f : 0.0f;
    }
}

// ---------------------------------------------------------------------------
extern "C" void kernel_launch(void* const* d_in, const int* in_sizes, int n_in,
                              void* d_out, int out_size) {
    const float* feat   = (const float*)d_in[0];
    const float* conv_w = (const float*)d_in[1];
    const float* conv_b = (const float*)d_in[2];
    const float* obj_w  = (const float*)d_in[3];
    const float* obj_b  = (const float*)d_in[4];
    const float* reg_w  = (const float*)d_in[5];
    const float* reg_b  = (const float*)d_in[6];
    float* out = (float*)d_out;

    cudaFuncSetAttribute(conv_mma_kernel, cudaFuncAttributeMaxDynamicSharedMemorySize, CONV_SMEM);
    cudaFuncSetAttribute(topk_nms_kernel, cudaFuncAttributeMaxDynamicSharedMemorySize, TK_SMEM);

    splitw_pad_kernel<<<3072 + NB, 256>>>(conv_w);
    dim3 sgrid(NL/64, NC/64, NB);
    splitfeat_kernel<<<sgrid, 256>>>(feat);

    dim3 cgrid(4, NL/128, NB);               // x=ob (F-tile sharing CTAs adjacent)
    conv_mma_kernel<<<cgrid, 256, CONV_SMEM>>>(conv_b, obj_w, reg_w);

    dim3 dgrid((NA*NL)/256, NB);             // (224, 8)
    decode_kernel<<<dgrid, 256>>>(obj_b, reg_b, out);

    topk_nms_kernel<<<NB, 512, TK_SMEM>>>(out);
}